// round 2
// baseline (speedup 1.0000x reference)
#include <cuda_runtime.h>
#include <math.h>

// Problem constants
#define BB      4
#define SS      4096
#define DD      768
#define NHH     8
#define DKV     64
#define PROJ    512          // NH*DK = NH*DV
#define NTOK    16384        // B*S
#define CHUNK   128
#define NC      32           // S / CHUNK
#define STATE_SZ 32768       // NH*DK*DV

// ---------------- device scratch (static, no allocation) ----------------
__device__ float g_q   [NTOK * PROJ];       // q for all batches
__device__ float g_k0  [SS * PROJ];         // k, batch 0 only
__device__ float g_v0  [SS * PROJ];         // v, batch 0 only
__device__ float g_g0  [SS * NHH];          // gate, batch 0 only
__device__ float g_W   [NC * STATE_SZ];     // per-chunk decayed write sums
__device__ float g_Fst [NC * STATE_SZ];     // state at each chunk start
__device__ float g_retr[NTOK * PROJ];       // retrieved
__device__ float g_dpow[136];               // 0.95^i, i=0..128

// ---------------- decay power table ----------------
__global__ void dpow_init_kernel() {
    if (threadIdx.x == 0 && blockIdx.x == 0) {
        double p = 1.0;
        for (int i = 0; i <= 128; i++) { g_dpow[i] = (float)p; p *= 0.95; }
    }
}

// ---------------- generic SGEMM: C = A(MxK) @ B(NxK)^T (+ Cadd) ----------------
// 128x128 block tile, BK=16, 256 threads, 8x8 microtile.
__global__ __launch_bounds__(256) void sgemm_nt(
    const float* __restrict__ A, const float* __restrict__ Bm,
    const float* __restrict__ Cadd, float* __restrict__ C,
    int M, int N, int K)
{
    __shared__ float As[16][132];
    __shared__ float Bs[16][132];

    int t  = threadIdx.x;
    int tx = t & 15, ty = t >> 4;
    int lr = t >> 2;            // 0..63
    int lc = (t & 3) << 2;      // 0,4,8,12

    const float* Ab = A  + (size_t)(blockIdx.y * 128) * K;
    const float* Bb = Bm + (size_t)(blockIdx.x * 128) * K;

    float acc[8][8];
#pragma unroll
    for (int i = 0; i < 8; i++)
#pragma unroll
        for (int j = 0; j < 8; j++) acc[i][j] = 0.f;

    for (int k0 = 0; k0 < K; k0 += 16) {
        float4 a0 = *(const float4*)(Ab + (size_t)lr        * K + k0 + lc);
        float4 a1 = *(const float4*)(Ab + (size_t)(lr + 64) * K + k0 + lc);
        float4 b0 = *(const float4*)(Bb + (size_t)lr        * K + k0 + lc);
        float4 b1 = *(const float4*)(Bb + (size_t)(lr + 64) * K + k0 + lc);

        As[lc+0][lr]    = a0.x; As[lc+1][lr]    = a0.y; As[lc+2][lr]    = a0.z; As[lc+3][lr]    = a0.w;
        As[lc+0][lr+64] = a1.x; As[lc+1][lr+64] = a1.y; As[lc+2][lr+64] = a1.z; As[lc+3][lr+64] = a1.w;
        Bs[lc+0][lr]    = b0.x; Bs[lc+1][lr]    = b0.y; Bs[lc+2][lr]    = b0.z; Bs[lc+3][lr]    = b0.w;
        Bs[lc+0][lr+64] = b1.x; Bs[lc+1][lr+64] = b1.y; Bs[lc+2][lr+64] = b1.z; Bs[lc+3][lr+64] = b1.w;
        __syncthreads();

#pragma unroll
        for (int kk = 0; kk < 16; kk++) {
            float ar[8], br[8];
            *(float4*)&ar[0] = *(const float4*)&As[kk][ty * 8];
            *(float4*)&ar[4] = *(const float4*)&As[kk][ty * 8 + 4];
            *(float4*)&br[0] = *(const float4*)&Bs[kk][tx * 8];
            *(float4*)&br[4] = *(const float4*)&Bs[kk][tx * 8 + 4];
#pragma unroll
            for (int i = 0; i < 8; i++)
#pragma unroll
                for (int j = 0; j < 8; j++)
                    acc[i][j] += ar[i] * br[j];
        }
        __syncthreads();
    }

    int row0 = blockIdx.y * 128 + ty * 8;
    int col0 = blockIdx.x * 128 + tx * 8;
#pragma unroll
    for (int i = 0; i < 8; i++) {
        size_t off = (size_t)(row0 + i) * N + col0;
        float4 o0 = make_float4(acc[i][0], acc[i][1], acc[i][2], acc[i][3]);
        float4 o1 = make_float4(acc[i][4], acc[i][5], acc[i][6], acc[i][7]);
        if (Cadd) {
            float4 x0 = *(const float4*)(Cadd + off);
            float4 x1 = *(const float4*)(Cadd + off + 4);
            o0.x += x0.x; o0.y += x0.y; o0.z += x0.z; o0.w += x0.w;
            o1.x += x1.x; o1.y += x1.y; o1.z += x1.z; o1.w += x1.w;
        }
        *(float4*)(C + off)     = o0;
        *(float4*)(C + off + 4) = o1;
    }
}

// ---------------- gate: g0[t,h] = sigmoid(x0[t,:] . wg[h,:]) ----------------
__global__ __launch_bounds__(256) void gate_kernel(
    const float* __restrict__ x, const float* __restrict__ wg)
{
    int warp = (blockIdx.x * blockDim.x + threadIdx.x) >> 5;
    int lane = threadIdx.x & 31;
    if (warp >= SS) return;
    float acc[NHH];
#pragma unroll
    for (int h = 0; h < NHH; h++) acc[h] = 0.f;
    const float* xr = x + (size_t)warp * DD;
    for (int d = lane; d < DD; d += 32) {
        float xv = xr[d];
#pragma unroll
        for (int h = 0; h < NHH; h++) acc[h] += xv * wg[h * DD + d];
    }
#pragma unroll
    for (int h = 0; h < NHH; h++) {
        float v = acc[h];
#pragma unroll
        for (int o = 16; o > 0; o >>= 1) v += __shfl_down_sync(0xffffffffu, v, o);
        if (lane == 0) g_g0[warp * NHH + h] = 1.f / (1.f + expf(-v));
    }
}

// ---------------- per-chunk decayed write sum: W_c[h] = K_hat^T V ----------------
// grid (NH, NC), 256 threads, 4x4 microtile of the 64x64 output.
__global__ __launch_bounds__(256) void chunkw_kernel()
{
    __shared__ float Ks[32][68];
    __shared__ float Vs[32][68];
    int h = blockIdx.x, c = blockIdx.y;
    int t = threadIdx.x, tx = t & 15, ty = t >> 4;

    float acc[4][4];
#pragma unroll
    for (int i = 0; i < 4; i++)
#pragma unroll
        for (int j = 0; j < 4; j++) acc[i][j] = 0.f;

    for (int jt = 0; jt < 4; jt++) {
#pragma unroll
        for (int pp = 0; pp < 2; pp++) {
            int p = t * 2 + pp;
            int j = p >> 4, kk4 = (p & 15) << 2;
            int row = c * CHUNK + jt * 32 + j;
            float s = g_dpow[127 - (jt * 32 + j)] * 0.1f * g_g0[row * NHH + h];
            float4 kv = *(const float4*)(g_k0 + (size_t)row * PROJ + h * 64 + kk4);
            Ks[j][kk4+0] = kv.x * s; Ks[j][kk4+1] = kv.y * s;
            Ks[j][kk4+2] = kv.z * s; Ks[j][kk4+3] = kv.w * s;
            float4 vv = *(const float4*)(g_v0 + (size_t)row * PROJ + h * 64 + kk4);
            Vs[j][kk4+0] = vv.x; Vs[j][kk4+1] = vv.y;
            Vs[j][kk4+2] = vv.z; Vs[j][kk4+3] = vv.w;
        }
        __syncthreads();
#pragma unroll
        for (int j = 0; j < 32; j++) {
            float kr[4], vr[4];
            *(float4*)kr = *(const float4*)&Ks[j][ty * 4];
            *(float4*)vr = *(const float4*)&Vs[j][tx * 4];
#pragma unroll
            for (int ii = 0; ii < 4; ii++)
#pragma unroll
                for (int jj = 0; jj < 4; jj++)
                    acc[ii][jj] += kr[ii] * vr[jj];
        }
        __syncthreads();
    }
#pragma unroll
    for (int ii = 0; ii < 4; ii++) {
        float4 o = make_float4(acc[ii][0], acc[ii][1], acc[ii][2], acc[ii][3]);
        *(float4*)(g_W + ((size_t)(c * NHH + h) * 64 + ty * 4 + ii) * 64 + tx * 4) = o;
    }
}

// ---------------- elementwise state prefix scan over chunks ----------------
__global__ void scan_kernel()
{
    int e = blockIdx.x * blockDim.x + threadIdx.x;   // 0..32767
    float fw = 0.f;
    float dc = g_dpow[128];
#pragma unroll 1
    for (int c = 0; c < NC; c++) {
        g_Fst[(size_t)c * STATE_SZ + e] = fw;
        fw = dc * fw + g_W[(size_t)c * STATE_SZ + e];
    }
}

// ---------------- retrieval: R = Lam*(Q F) + (mask.decay.gate . QK^T) V ----------------
// grid (NH, NC, B), 256 threads, dynamic smem.
#define QS_STR 68
#define AS_STR 33
#define SM_QS  0
#define SM_FS  (128*68)
#define SM_AS  (128*68 + 64*68)
#define SM_KT  (128*68 + 64*68 + 128*33)
#define SM_VT  (SM_KT + 32*68)
#define SM_SG  (SM_VT + 32*68)
#define RETR_SMEM_BYTES ((SM_SG + 128) * 4)

__global__ __launch_bounds__(256) void retrieve_kernel()
{
    extern __shared__ float sm[];
    float* Qs  = sm + SM_QS;
    float* Fs  = sm + SM_FS;
    float* Asm = sm + SM_AS;
    float* Kt  = sm + SM_KT;
    float* Vt  = sm + SM_VT;
    float* sg  = sm + SM_SG;

    int h = blockIdx.x, c = blockIdx.y, b = blockIdx.z;
    int t = threadIdx.x;

    // load Q chunk (128 x 64)
#pragma unroll
    for (int pp = 0; pp < 8; pp++) {
        int p = t + 256 * pp;                 // 0..2047
        int i = p >> 4, kk4 = (p & 15) << 2;
        int row = b * SS + c * CHUNK + i;
        float4 v = *(const float4*)(g_q + (size_t)row * PROJ + h * 64 + kk4);
        Qs[i * QS_STR + kk4+0] = v.x; Qs[i * QS_STR + kk4+1] = v.y;
        Qs[i * QS_STR + kk4+2] = v.z; Qs[i * QS_STR + kk4+3] = v.w;
    }
    // load F state (64 x 64)
#pragma unroll
    for (int pp = 0; pp < 4; pp++) {
        int p = t + 256 * pp;                 // 0..1023
        int kk = p >> 4, vv4 = (p & 15) << 2;
        float4 v = *(const float4*)(g_Fst + (size_t)c * STATE_SZ + h * 4096 + kk * 64 + vv4);
        Fs[kk * QS_STR + vv4+0] = v.x; Fs[kk * QS_STR + vv4+1] = v.y;
        Fs[kk * QS_STR + vv4+2] = v.z; Fs[kk * QS_STR + vv4+3] = v.w;
    }
    if (t < 128) sg[t] = 0.1f * g_g0[(c * CHUNK + t) * NHH + h];
    __syncthreads();

    int rx = t & 15, ry = t >> 4;   // R microtile: rows ry*8..+8, cols rx*4..+4
    float racc[8][4];
#pragma unroll
    for (int i = 0; i < 8; i++)
#pragma unroll
        for (int j = 0; j < 4; j++) racc[i][j] = 0.f;

    // inter-chunk: Q @ F
#pragma unroll 4
    for (int kk = 0; kk < 64; kk++) {
        float4 fv = *(const float4*)&Fs[kk * QS_STR + rx * 4];
#pragma unroll
        for (int ii = 0; ii < 8; ii++) {
            float qv = Qs[(ry * 8 + ii) * QS_STR + kk];
            racc[ii][0] += qv * fv.x; racc[ii][1] += qv * fv.y;
            racc[ii][2] += qv * fv.z; racc[ii][3] += qv * fv.w;
        }
    }
    // scale by Lambda_i = decay^i
#pragma unroll
    for (int ii = 0; ii < 8; ii++) {
        float lam = g_dpow[ry * 8 + ii];
        racc[ii][0] *= lam; racc[ii][1] *= lam; racc[ii][2] *= lam; racc[ii][3] *= lam;
    }

    int ax = t & 7, ay = t >> 3;    // A microtile: rows ay*4..+4, local cols ax*4..+4

    for (int jt = 0; jt < 4; jt++) {
        __syncthreads();            // previous AV done before Kt/Vt/Asm reuse
        // load K/V tile (32 rows)
#pragma unroll
        for (int pp = 0; pp < 2; pp++) {
            int p = t * 2 + pp;
            int j = p >> 4, kk4 = (p & 15) << 2;
            int row = c * CHUNK + jt * 32 + j;
            float4 kv = *(const float4*)(g_k0 + (size_t)row * PROJ + h * 64 + kk4);
            Kt[j * QS_STR + kk4+0] = kv.x; Kt[j * QS_STR + kk4+1] = kv.y;
            Kt[j * QS_STR + kk4+2] = kv.z; Kt[j * QS_STR + kk4+3] = kv.w;
            float4 vv = *(const float4*)(g_v0 + (size_t)row * PROJ + h * 64 + kk4);
            Vt[j * QS_STR + kk4+0] = vv.x; Vt[j * QS_STR + kk4+1] = vv.y;
            Vt[j * QS_STR + kk4+2] = vv.z; Vt[j * QS_STR + kk4+3] = vv.w;
        }
        __syncthreads();

        // A tile: (128 x 32) = Q . K^T with mask/decay/gate weights
        float aacc[4][4];
#pragma unroll
        for (int i = 0; i < 4; i++)
#pragma unroll
            for (int j = 0; j < 4; j++) aacc[i][j] = 0.f;
#pragma unroll 4
        for (int kk4 = 0; kk4 < 64; kk4 += 4) {
            float4 qv[4], kv[4];
#pragma unroll
            for (int ii = 0; ii < 4; ii++)
                qv[ii] = *(const float4*)&Qs[(ay * 4 + ii) * QS_STR + kk4];
#pragma unroll
            for (int jj = 0; jj < 4; jj++)
                kv[jj] = *(const float4*)&Kt[(ax * 4 + jj) * QS_STR + kk4];
#pragma unroll
            for (int ii = 0; ii < 4; ii++)
#pragma unroll
                for (int jj = 0; jj < 4; jj++)
                    aacc[ii][jj] += qv[ii].x * kv[jj].x + qv[ii].y * kv[jj].y
                                  + qv[ii].z * kv[jj].z + qv[ii].w * kv[jj].w;
        }
#pragma unroll
        for (int ii = 0; ii < 4; ii++) {
            int i = ay * 4 + ii;
#pragma unroll
            for (int jj = 0; jj < 4; jj++) {
                int jl = ax * 4 + jj;
                int jg = jt * 32 + jl;
                float w = (jg < i) ? g_dpow[i - 1 - jg] * sg[jg] : 0.f;
                Asm[i * AS_STR + jl] = aacc[ii][jj] * w;
            }
        }
        __syncthreads();

        // R += A_tile @ V_tile
#pragma unroll 8
        for (int j = 0; j < 32; j++) {
            float4 vv = *(const float4*)&Vt[j * QS_STR + rx * 4];
#pragma unroll
            for (int ii = 0; ii < 8; ii++) {
                float a = Asm[(ry * 8 + ii) * AS_STR + j];
                racc[ii][0] += a * vv.x; racc[ii][1] += a * vv.y;
                racc[ii][2] += a * vv.z; racc[ii][3] += a * vv.w;
            }
        }
    }

    // store R
#pragma unroll
    for (int ii = 0; ii < 8; ii++) {
        int row = b * SS + c * CHUNK + ry * 8 + ii;
        float4 o = make_float4(racc[ii][0], racc[ii][1], racc[ii][2], racc[ii][3]);
        *(float4*)(g_retr + (size_t)row * PROJ + h * 64 + rx * 4) = o;
    }
}

// ---------------- host launch ----------------
extern "C" void kernel_launch(void* const* d_in, const int* in_sizes, int n_in,
                              void* d_out, int out_size)
{
    (void)in_sizes; (void)n_in; (void)out_size;
    const float* x  = (const float*)d_in[0];
    const float* wk = (const float*)d_in[1];
    const float* wv = (const float*)d_in[2];
    const float* wq = (const float*)d_in[3];
    const float* wg = (const float*)d_in[4];
    const float* wo = (const float*)d_in[5];
    float* out = (float*)d_out;

    float *qp, *k0p, *v0p, *retrp;
    cudaGetSymbolAddress((void**)&qp,    g_q);
    cudaGetSymbolAddress((void**)&k0p,   g_k0);
    cudaGetSymbolAddress((void**)&v0p,   g_v0);
    cudaGetSymbolAddress((void**)&retrp, g_retr);

    cudaFuncSetAttribute(retrieve_kernel,
                         cudaFuncAttributeMaxDynamicSharedMemorySize,
                         RETR_SMEM_BYTES);

    dpow_init_kernel<<<1, 1>>>();

    // projections (k/v/gate only need batch 0)
    sgemm_nt<<<dim3(4, 128), 256>>>(x, wq, nullptr, qp,  NTOK, PROJ, DD);
    sgemm_nt<<<dim3(4, 32),  256>>>(x, wk, nullptr, k0p, SS,   PROJ, DD);
    sgemm_nt<<<dim3(4, 32),  256>>>(x, wv, nullptr, v0p, SS,   PROJ, DD);
    gate_kernel<<<512, 256>>>(x, wg);

    // chunked linear-attention decomposition of the scan
    chunkw_kernel<<<dim3(NHH, NC), 256>>>();
    scan_kernel<<<128, 256>>>();
    retrieve_kernel<<<dim3(NHH, NC, BB), 256, RETR_SMEM_BYTES>>>();

    // out = x + retrieved @ w_out^T
    sgemm_nt<<<dim3(6, 128), 256>>>(retrp, wo, x, out, NTOK, DD, PROJ);
}

// round 5
// speedup vs baseline: 1.3325x; 1.3325x over previous
#include <cuda_runtime.h>
#include <stdint.h>
#include <math.h>

// Problem constants
#define BB      4
#define SS      4096
#define DD      768
#define NHH     8
#define DKV     64
#define PROJ    512          // NH*DK = NH*DV
#define NTOK    16384        // B*S
#define CHUNK   128
#define NC      32           // S / CHUNK
#define STATE_SZ 32768       // NH*DK*DV

// ---------------- device scratch (static, no allocation) ----------------
__device__ float g_q   [NTOK * PROJ];       // q for all batches
__device__ float g_k0  [SS * PROJ];         // k, batch 0 only
__device__ float g_v0  [SS * PROJ];         // v, batch 0 only
__device__ float g_g0  [SS * NHH];          // gate, batch 0 only
__device__ float g_W   [NC * STATE_SZ];     // per-chunk decayed write sums
__device__ float g_Fst [NC * STATE_SZ];     // state at each chunk start
__device__ float g_retr[NTOK * PROJ];       // retrieved
__device__ float g_dpow[136];               // 0.95^i, i=0..128

// ---------------- decay power table ----------------
__global__ void dpow_init_kernel() {
    if (threadIdx.x == 0 && blockIdx.x == 0) {
        double p = 1.0;
        for (int i = 0; i <= 128; i++) { g_dpow[i] = (float)p; p *= 0.95; }
    }
}

// ---------------- tf32 helpers ----------------
__device__ __forceinline__ float to_tf32(float x) {
    uint32_t u;
    asm("cvt.rna.tf32.f32 %0, %1;" : "=r"(u) : "f"(x));
    return __uint_as_float(u);
}

#define MMA_TF32(d, a, b)                                                     \
    asm volatile("mma.sync.aligned.m16n8k8.row.col.f32.tf32.tf32.f32 "        \
                 "{%0,%1,%2,%3}, {%4,%5,%6,%7}, {%8,%9}, {%0,%1,%2,%3};"      \
                 : "+f"((d)[0]), "+f"((d)[1]), "+f"((d)[2]), "+f"((d)[3])     \
                 : "r"((a)[0]), "r"((a)[1]), "r"((a)[2]), "r"((a)[3]),        \
                   "r"((b)[0]), "r"((b)[1]))

// ---------------- tf32 tensor-core GEMM: C = A(MxK) @ B(NxK)^T (+ Cadd) ----
// 128x128 block tile, BK=32, 256 threads = 8 warps (2x4), warp tile 64x32.
// Smem k-major [c][r] with stride 136 (== 8 mod 32 -> conflict-free frags).
#define TG_STR   136
#define TG_BUF   (32 * TG_STR)                 // floats per buffer
#define TG_SMEM  (4 * TG_BUF * 4)              // bytes: As[2] + Bs[2]

__global__ void __launch_bounds__(256) tgemm_nt(
    const float* __restrict__ A, const float* __restrict__ Bm,
    const float* __restrict__ Cadd, float* __restrict__ C,
    int M, int N, int K)
{
    extern __shared__ float sm[];
    float* As = sm;                    // [2][32][136]
    float* Bs = sm + 2 * TG_BUF;       // [2][32][136]

    int t    = threadIdx.x;
    int warp = t >> 5, lane = t & 31;
    int wm = warp >> 2, wn = warp & 3;     // warp grid 2 x 4
    int lr = lane >> 2, lc = lane & 3;     // fragment lane decomposition

    const float* Ab = A  + (size_t)(blockIdx.y * 128) * K;
    const float* Bb = Bm + (size_t)(blockIdx.x * 128) * K;

    int ldr = t & 127;                 // loader: row within tile
    int ldc = (t >> 7) * 16;           // loader: col base (0 or 16)

    float acc[4][4][4];
#pragma unroll
    for (int i = 0; i < 4; i++)
#pragma unroll
        for (int j = 0; j < 4; j++)
#pragma unroll
            for (int r = 0; r < 4; r++) acc[i][j][r] = 0.f;

    const int NIT = K >> 5;            // K / 32
    float4 stA[4], stB[4];

    // preload iter 0 into registers
#pragma unroll
    for (int i = 0; i < 4; i++) {
        stA[i] = *(const float4*)(Ab + (size_t)ldr * K + ldc + 4 * i);
        stB[i] = *(const float4*)(Bb + (size_t)ldr * K + ldc + 4 * i);
    }
    // store buf 0 (transposed, tf32-rounded)
#pragma unroll
    for (int i = 0; i < 4; i++) {
        int cb = ldc + 4 * i;
        As[(cb+0)*TG_STR + ldr] = to_tf32(stA[i].x);
        As[(cb+1)*TG_STR + ldr] = to_tf32(stA[i].y);
        As[(cb+2)*TG_STR + ldr] = to_tf32(stA[i].z);
        As[(cb+3)*TG_STR + ldr] = to_tf32(stA[i].w);
        Bs[(cb+0)*TG_STR + ldr] = to_tf32(stB[i].x);
        Bs[(cb+1)*TG_STR + ldr] = to_tf32(stB[i].y);
        Bs[(cb+2)*TG_STR + ldr] = to_tf32(stB[i].z);
        Bs[(cb+3)*TG_STR + ldr] = to_tf32(stB[i].w);
    }
    __syncthreads();

    for (int it = 0; it < NIT; it++) {
        // prefetch next tile into registers
        if (it + 1 < NIT) {
            int kg = (it + 1) * 32 + ldc;
#pragma unroll
            for (int i = 0; i < 4; i++) {
                stA[i] = *(const float4*)(Ab + (size_t)ldr * K + kg + 4 * i);
                stB[i] = *(const float4*)(Bb + (size_t)ldr * K + kg + 4 * i);
            }
        }

        const float* Ac = As + (it & 1) * TG_BUF;
        const float* Bc = Bs + (it & 1) * TG_BUF;

#pragma unroll
        for (int ks = 0; ks < 4; ks++) {
            int c0 = ks * 8 + lc;
            uint32_t af[4][4];
#pragma unroll
            for (int mt = 0; mt < 4; mt++) {
                int r0 = wm * 64 + mt * 16 + lr;
                af[mt][0] = __float_as_uint(Ac[(c0    )*TG_STR + r0    ]);
                af[mt][1] = __float_as_uint(Ac[(c0    )*TG_STR + r0 + 8]);
                af[mt][2] = __float_as_uint(Ac[(c0 + 4)*TG_STR + r0    ]);
                af[mt][3] = __float_as_uint(Ac[(c0 + 4)*TG_STR + r0 + 8]);
            }
            uint32_t bf[4][2];
#pragma unroll
            for (int nt = 0; nt < 4; nt++) {
                int n0 = wn * 32 + nt * 8 + lr;
                bf[nt][0] = __float_as_uint(Bc[(c0    )*TG_STR + n0]);
                bf[nt][1] = __float_as_uint(Bc[(c0 + 4)*TG_STR + n0]);
            }
#pragma unroll
            for (int mt = 0; mt < 4; mt++)
#pragma unroll
                for (int nt = 0; nt < 4; nt++)
                    MMA_TF32(acc[mt][nt], af[mt], bf[nt]);
        }

        if (it + 1 < NIT) {
            float* Ad = As + ((it + 1) & 1) * TG_BUF;
            float* Bd = Bs + ((it + 1) & 1) * TG_BUF;
#pragma unroll
            for (int i = 0; i < 4; i++) {
                int cb = ldc + 4 * i;
                Ad[(cb+0)*TG_STR + ldr] = to_tf32(stA[i].x);
                Ad[(cb+1)*TG_STR + ldr] = to_tf32(stA[i].y);
                Ad[(cb+2)*TG_STR + ldr] = to_tf32(stA[i].z);
                Ad[(cb+3)*TG_STR + ldr] = to_tf32(stA[i].w);
                Bd[(cb+0)*TG_STR + ldr] = to_tf32(stB[i].x);
                Bd[(cb+1)*TG_STR + ldr] = to_tf32(stB[i].y);
                Bd[(cb+2)*TG_STR + ldr] = to_tf32(stB[i].z);
                Bd[(cb+3)*TG_STR + ldr] = to_tf32(stB[i].w);
            }
            __syncthreads();
        }
    }

    // epilogue: C fragment layout (row = lr, cols 2*lc, 2*lc+1; + row+8)
#pragma unroll
    for (int mt = 0; mt < 4; mt++) {
#pragma unroll
        for (int nt = 0; nt < 4; nt++) {
            int r = blockIdx.y * 128 + wm * 64 + mt * 16 + lr;
            int c = blockIdx.x * 128 + wn * 32 + nt * 8 + 2 * lc;
            size_t off0 = (size_t)r * N + c;
            size_t off1 = (size_t)(r + 8) * N + c;
            float2 lo = make_float2(acc[mt][nt][0], acc[mt][nt][1]);
            float2 hi = make_float2(acc[mt][nt][2], acc[mt][nt][3]);
            if (Cadd) {
                float2 x0 = *(const float2*)(Cadd + off0);
                float2 x1 = *(const float2*)(Cadd + off1);
                lo.x += x0.x; lo.y += x0.y;
                hi.x += x1.x; hi.y += x1.y;
            }
            *(float2*)(C + off0) = lo;
            *(float2*)(C + off1) = hi;
        }
    }
}

// ---------------- gate: g0[t,h] = sigmoid(x0[t,:] . wg[h,:]) ----------------
__global__ __launch_bounds__(256) void gate_kernel(
    const float* __restrict__ x, const float* __restrict__ wg)
{
    int warp = (blockIdx.x * blockDim.x + threadIdx.x) >> 5;
    int lane = threadIdx.x & 31;
    if (warp >= SS) return;
    float acc[NHH];
#pragma unroll
    for (int h = 0; h < NHH; h++) acc[h] = 0.f;
    const float* xr = x + (size_t)warp * DD;
    for (int d = lane; d < DD; d += 32) {
        float xv = xr[d];
#pragma unroll
        for (int h = 0; h < NHH; h++) acc[h] += xv * wg[h * DD + d];
    }
#pragma unroll
    for (int h = 0; h < NHH; h++) {
        float v = acc[h];
#pragma unroll
        for (int o = 16; o > 0; o >>= 1) v += __shfl_down_sync(0xffffffffu, v, o);
        if (lane == 0) g_g0[warp * NHH + h] = 1.f / (1.f + expf(-v));
    }
}

// ---------------- per-chunk decayed write sum: W_c[h] = K_hat^T V ----------------
__global__ __launch_bounds__(256) void chunkw_kernel()
{
    __shared__ float Ks[32][68];
    __shared__ float Vs[32][68];
    int h = blockIdx.x, c = blockIdx.y;
    int t = threadIdx.x, tx = t & 15, ty = t >> 4;

    float acc[4][4];
#pragma unroll
    for (int i = 0; i < 4; i++)
#pragma unroll
        for (int j = 0; j < 4; j++) acc[i][j] = 0.f;

    for (int jt = 0; jt < 4; jt++) {
#pragma unroll
        for (int pp = 0; pp < 2; pp++) {
            int p = t * 2 + pp;
            int j = p >> 4, kk4 = (p & 15) << 2;
            int row = c * CHUNK + jt * 32 + j;
            float s = g_dpow[127 - (jt * 32 + j)] * 0.1f * g_g0[row * NHH + h];
            float4 kv = *(const float4*)(g_k0 + (size_t)row * PROJ + h * 64 + kk4);
            Ks[j][kk4+0] = kv.x * s; Ks[j][kk4+1] = kv.y * s;
            Ks[j][kk4+2] = kv.z * s; Ks[j][kk4+3] = kv.w * s;
            float4 vv = *(const float4*)(g_v0 + (size_t)row * PROJ + h * 64 + kk4);
            Vs[j][kk4+0] = vv.x; Vs[j][kk4+1] = vv.y;
            Vs[j][kk4+2] = vv.z; Vs[j][kk4+3] = vv.w;
        }
        __syncthreads();
#pragma unroll
        for (int j = 0; j < 32; j++) {
            float kr[4], vr[4];
            *(float4*)kr = *(const float4*)&Ks[j][ty * 4];
            *(float4*)vr = *(const float4*)&Vs[j][tx * 4];
#pragma unroll
            for (int ii = 0; ii < 4; ii++)
#pragma unroll
                for (int jj = 0; jj < 4; jj++)
                    acc[ii][jj] += kr[ii] * vr[jj];
        }
        __syncthreads();
    }
#pragma unroll
    for (int ii = 0; ii < 4; ii++) {
        float4 o = make_float4(acc[ii][0], acc[ii][1], acc[ii][2], acc[ii][3]);
        *(float4*)(g_W + ((size_t)(c * NHH + h) * 64 + ty * 4 + ii) * 64 + tx * 4) = o;
    }
}

// ---------------- elementwise state prefix scan over chunks ----------------
__global__ void scan_kernel()
{
    int e = blockIdx.x * blockDim.x + threadIdx.x;   // 0..32767
    float fw = 0.f;
    float dc = g_dpow[128];
#pragma unroll 1
    for (int c = 0; c < NC; c++) {
        g_Fst[(size_t)c * STATE_SZ + e] = fw;
        fw = dc * fw + g_W[(size_t)c * STATE_SZ + e];
    }
}

// ---------------- retrieval: R = Lam*(Q F) + (mask.decay.gate . QK^T) V ----------------
#define QS_STR 68
#define AS_STR 33
#define SM_QS  0
#define SM_FS  (128*68)
#define SM_AS  (128*68 + 64*68)
#define SM_KT  (128*68 + 64*68 + 128*33)
#define SM_VT  (SM_KT + 32*68)
#define SM_SG  (SM_VT + 32*68)
#define RETR_SMEM_BYTES ((SM_SG + 128) * 4)

__global__ __launch_bounds__(256) void retrieve_kernel()
{
    extern __shared__ float sm[];
    float* Qs  = sm + SM_QS;
    float* Fs  = sm + SM_FS;
    float* Asm = sm + SM_AS;
    float* Kt  = sm + SM_KT;
    float* Vt  = sm + SM_VT;
    float* sg  = sm + SM_SG;

    int h = blockIdx.x, c = blockIdx.y, b = blockIdx.z;
    int t = threadIdx.x;

#pragma unroll
    for (int pp = 0; pp < 8; pp++) {
        int p = t + 256 * pp;
        int i = p >> 4, kk4 = (p & 15) << 2;
        int row = b * SS + c * CHUNK + i;
        float4 v = *(const float4*)(g_q + (size_t)row * PROJ + h * 64 + kk4);
        Qs[i * QS_STR + kk4+0] = v.x; Qs[i * QS_STR + kk4+1] = v.y;
        Qs[i * QS_STR + kk4+2] = v.z; Qs[i * QS_STR + kk4+3] = v.w;
    }
#pragma unroll
    for (int pp = 0; pp < 4; pp++) {
        int p = t + 256 * pp;
        int kk = p >> 4, vv4 = (p & 15) << 2;
        float4 v = *(const float4*)(g_Fst + (size_t)c * STATE_SZ + h * 4096 + kk * 64 + vv4);
        Fs[kk * QS_STR + vv4+0] = v.x; Fs[kk * QS_STR + vv4+1] = v.y;
        Fs[kk * QS_STR + vv4+2] = v.z; Fs[kk * QS_STR + vv4+3] = v.w;
    }
    if (t < 128) sg[t] = 0.1f * g_g0[(c * CHUNK + t) * NHH + h];
    __syncthreads();

    int rx = t & 15, ry = t >> 4;
    float racc[8][4];
#pragma unroll
    for (int i = 0; i < 8; i++)
#pragma unroll
        for (int j = 0; j < 4; j++) racc[i][j] = 0.f;

#pragma unroll 4
    for (int kk = 0; kk < 64; kk++) {
        float4 fv = *(const float4*)&Fs[kk * QS_STR + rx * 4];
#pragma unroll
        for (int ii = 0; ii < 8; ii++) {
            float qv = Qs[(ry * 8 + ii) * QS_STR + kk];
            racc[ii][0] += qv * fv.x; racc[ii][1] += qv * fv.y;
            racc[ii][2] += qv * fv.z; racc[ii][3] += qv * fv.w;
        }
    }
#pragma unroll
    for (int ii = 0; ii < 8; ii++) {
        float lam = g_dpow[ry * 8 + ii];
        racc[ii][0] *= lam; racc[ii][1] *= lam; racc[ii][2] *= lam; racc[ii][3] *= lam;
    }

    int ax = t & 7, ay = t >> 3;

    for (int jt = 0; jt < 4; jt++) {
        __syncthreads();
#pragma unroll
        for (int pp = 0; pp < 2; pp++) {
            int p = t * 2 + pp;
            int j = p >> 4, kk4 = (p & 15) << 2;
            int row = c * CHUNK + jt * 32 + j;
            float4 kv = *(const float4*)(g_k0 + (size_t)row * PROJ + h * 64 + kk4);
            Kt[j * QS_STR + kk4+0] = kv.x; Kt[j * QS_STR + kk4+1] = kv.y;
            Kt[j * QS_STR + kk4+2] = kv.z; Kt[j * QS_STR + kk4+3] = kv.w;
            float4 vv = *(const float4*)(g_v0 + (size_t)row * PROJ + h * 64 + kk4);
            Vt[j * QS_STR + kk4+0] = vv.x; Vt[j * QS_STR + kk4+1] = vv.y;
            Vt[j * QS_STR + kk4+2] = vv.z; Vt[j * QS_STR + kk4+3] = vv.w;
        }
        __syncthreads();

        float aacc[4][4];
#pragma unroll
        for (int i = 0; i < 4; i++)
#pragma unroll
            for (int j = 0; j < 4; j++) aacc[i][j] = 0.f;
#pragma unroll 4
        for (int kk4 = 0; kk4 < 64; kk4 += 4) {
            float4 qv[4], kv[4];
#pragma unroll
            for (int ii = 0; ii < 4; ii++)
                qv[ii] = *(const float4*)&Qs[(ay * 4 + ii) * QS_STR + kk4];
#pragma unroll
            for (int jj = 0; jj < 4; jj++)
                kv[jj] = *(const float4*)&Kt[(ax * 4 + jj) * QS_STR + kk4];
#pragma unroll
            for (int ii = 0; ii < 4; ii++)
#pragma unroll
                for (int jj = 0; jj < 4; jj++)
                    aacc[ii][jj] += qv[ii].x * kv[jj].x + qv[ii].y * kv[jj].y
                                  + qv[ii].z * kv[jj].z + qv[ii].w * kv[jj].w;
        }
#pragma unroll
        for (int ii = 0; ii < 4; ii++) {
            int i = ay * 4 + ii;
#pragma unroll
            for (int jj = 0; jj < 4; jj++) {
                int jl = ax * 4 + jj;
                int jg = jt * 32 + jl;
                float w = (jg < i) ? g_dpow[i - 1 - jg] * sg[jg] : 0.f;
                Asm[i * AS_STR + jl] = aacc[ii][jj] * w;
            }
        }
        __syncthreads();

#pragma unroll 8
        for (int j = 0; j < 32; j++) {
            float4 vv = *(const float4*)&Vt[j * QS_STR + rx * 4];
#pragma unroll
            for (int ii = 0; ii < 8; ii++) {
                float a = Asm[(ry * 8 + ii) * AS_STR + j];
                racc[ii][0] += a * vv.x; racc[ii][1] += a * vv.y;
                racc[ii][2] += a * vv.z; racc[ii][3] += a * vv.w;
            }
        }
    }

#pragma unroll
    for (int ii = 0; ii < 8; ii++) {
        int row = b * SS + c * CHUNK + ry * 8 + ii;
        float4 o = make_float4(racc[ii][0], racc[ii][1], racc[ii][2], racc[ii][3]);
        *(float4*)(g_retr + (size_t)row * PROJ + h * 64 + rx * 4) = o;
    }
}

// ---------------- host launch ----------------
extern "C" void kernel_launch(void* const* d_in, const int* in_sizes, int n_in,
                              void* d_out, int out_size)
{
    (void)in_sizes; (void)n_in; (void)out_size;
    const float* x  = (const float*)d_in[0];
    const float* wk = (const float*)d_in[1];
    const float* wv = (const float*)d_in[2];
    const float* wq = (const float*)d_in[3];
    const float* wg = (const float*)d_in[4];
    const float* wo = (const float*)d_in[5];
    float* out = (float*)d_out;

    float *qp, *k0p, *v0p, *retrp;
    cudaGetSymbolAddress((void**)&qp,    g_q);
    cudaGetSymbolAddress((void**)&k0p,   g_k0);
    cudaGetSymbolAddress((void**)&v0p,   g_v0);
    cudaGetSymbolAddress((void**)&retrp, g_retr);

    cudaFuncSetAttribute(retrieve_kernel,
                         cudaFuncAttributeMaxDynamicSharedMemorySize,
                         RETR_SMEM_BYTES);
    cudaFuncSetAttribute(tgemm_nt,
                         cudaFuncAttributeMaxDynamicSharedMemorySize,
                         TG_SMEM);

    dpow_init_kernel<<<1, 1>>>();

    // projections on tensor cores (tf32); k/v/gate only need batch 0
    tgemm_nt<<<dim3(4, 128), 256, TG_SMEM>>>(x, wq, nullptr, qp,  NTOK, PROJ, DD);
    tgemm_nt<<<dim3(4, 32),  256, TG_SMEM>>>(x, wk, nullptr, k0p, SS,   PROJ, DD);
    tgemm_nt<<<dim3(4, 32),  256, TG_SMEM>>>(x, wv, nullptr, v0p, SS,   PROJ, DD);
    gate_kernel<<<512, 256>>>(x, wg);

    // chunked linear-attention decomposition of the scan
    chunkw_kernel<<<dim3(NHH, NC), 256>>>();
    scan_kernel<<<128, 256>>>();
    retrieve_kernel<<<dim3(NHH, NC, BB), 256, RETR_SMEM_BYTES>>>();

    // out = x + retrieved @ w_out^T
    tgemm_nt<<<dim3(6, 128), 256, TG_SMEM>>>(retrp, wo, x, out, NTOK, DD, PROJ);
}

// round 6
// speedup vs baseline: 1.6676x; 1.2515x over previous
#include <cuda_runtime.h>
#include <stdint.h>
#include <math.h>

// Problem constants
#define BB      4
#define SS      4096
#define DD      768
#define NHH     8
#define DKV     64
#define PROJ    512          // NH*DK = NH*DV
#define NTOK    16384        // B*S
#define CHUNK   128
#define NC      32           // S / CHUNK
#define STATE_SZ 32768       // NH*DK*DV

// ---------------- device scratch (static, no allocation) ----------------
__device__ float g_q   [NTOK * PROJ];       // q for all batches
__device__ float g_k0  [SS * PROJ];         // k, batch 0 only
__device__ float g_v0  [SS * PROJ];         // v, batch 0 only
__device__ float g_g0  [SS * NHH];          // gate, batch 0 only
__device__ float g_W   [NC * STATE_SZ];     // per-chunk decayed write sums
__device__ float g_Fst [NC * STATE_SZ];     // state at each chunk start
__device__ float g_retr[NTOK * PROJ];       // retrieved
__device__ float g_dpow[136];               // 0.95^i, i=0..128

// ---------------- decay power table ----------------
__global__ void dpow_init_kernel() {
    if (threadIdx.x == 0 && blockIdx.x == 0) {
        double p = 1.0;
        for (int i = 0; i <= 128; i++) { g_dpow[i] = (float)p; p *= 0.95; }
    }
}

// ---------------- tensor-core GEMM plumbing ----------------
#define MMA_TF32(d, a, b)                                                     \
    asm volatile("mma.sync.aligned.m16n8k8.row.col.f32.tf32.tf32.f32 "        \
                 "{%0,%1,%2,%3}, {%4,%5,%6,%7}, {%8,%9}, {%0,%1,%2,%3};"      \
                 : "+f"((d)[0]), "+f"((d)[1]), "+f"((d)[2]), "+f"((d)[3])     \
                 : "r"((a)[0]), "r"((a)[1]), "r"((a)[2]), "r"((a)[3]),        \
                   "r"((b)[0]), "r"((b)[1]))

#define LDSM4(r0, r1, r2, r3, addr)                                           \
    asm volatile("ldmatrix.sync.aligned.m8n8.x4.shared.b16 {%0,%1,%2,%3}, [%4];" \
                 : "=r"(r0), "=r"(r1), "=r"(r2), "=r"(r3) : "r"(addr))

#define CP_ASYNC16(dst, src)                                                  \
    asm volatile("cp.async.cg.shared.global [%0], [%1], 16;" :: "r"(dst), "l"(src))
#define CP_COMMIT() asm volatile("cp.async.commit_group;")
#define CP_WAIT1()  asm volatile("cp.async.wait_group 1;")
#define CP_WAIT0()  asm volatile("cp.async.wait_group 0;")

// Tiles: 128x128 block, BK=32, 256 threads = 8 warps (2x4), warp tile 64x32.
// Smem row-major, pitch 36 floats (144B, 16B-aligned rows, conflict-free:
// bank(r,c) = (4r + c) mod 32 distinct over any 8 consecutive rows).
#define TG_P      36
#define TG_BUFB   (128 * TG_P * 4)             // bytes per buffer (18432)
#define TG_SMEM   (4 * TG_BUFB)                // A[2] + B[2] = 73728 bytes

__device__ __forceinline__ void gemm_body(
    const float* __restrict__ A, const float* __restrict__ Bm,
    const float* __restrict__ Cadd, float* __restrict__ C,
    int N, int K, int bx, int by)
{
    extern __shared__ float smg[];
    uint32_t sA = (uint32_t)__cvta_generic_to_shared(smg);
    uint32_t sB = sA + 2 * TG_BUFB;

    int t    = threadIdx.x;
    int warp = t >> 5, lane = t & 31;
    int wm = warp >> 2, wn = warp & 3;     // warp grid 2 x 4
    int g  = lane >> 3, gr = lane & 7;     // ldmatrix groups
    int lr = lane >> 2, lc = lane & 3;     // mma C-fragment decomposition

    // loader: row ldr (0..127), col base ldc (0 or 16)
    int ldr = t & 127, ldc = (t >> 7) * 16;
    const float* gA = A  + (size_t)(by * 128 + ldr) * K + ldc;
    const float* gB = Bm + (size_t)(bx * 128 + ldr) * K + ldc;
    uint32_t dA = sA + (uint32_t)(ldr * TG_P + ldc) * 4;
    uint32_t dB = sB + (uint32_t)(ldr * TG_P + ldc) * 4;

    // ldmatrix per-thread addresses (buffer 0, ks 0); +oa and +ks*32 later.
    // A: matrix g covers rows (g&1)*8 + 0..7 of the mt tile, k-cols (g>>1)*4.
    uint32_t aAddr[4];
#pragma unroll
    for (int mt = 0; mt < 4; mt++)
        aAddr[mt] = sA + (uint32_t)(((wm * 64 + mt * 16 + (g & 1) * 8 + gr) * TG_P
                                     + (g >> 1) * 4) * 4);
    // B (n-major rows): matrix g covers n-rows (2np + (g>>1))*8 + 0..7, k-cols (g&1)*4.
    uint32_t bAddr[2];
#pragma unroll
    for (int np = 0; np < 2; np++)
        bAddr[np] = sB + (uint32_t)(((wn * 32 + (2 * np + (g >> 1)) * 8 + gr) * TG_P
                                     + (g & 1) * 4) * 4);

    float acc[4][4][4];
#pragma unroll
    for (int i = 0; i < 4; i++)
#pragma unroll
        for (int j = 0; j < 4; j++)
#pragma unroll
            for (int r = 0; r < 4; r++) acc[i][j][r] = 0.f;

    const int NIT = K >> 5;

    // prologue: issue groups for it=0 and it=1
#pragma unroll
    for (int i = 0; i < 4; i++) {
        CP_ASYNC16(dA + 16 * i, gA + 4 * i);
        CP_ASYNC16(dB + 16 * i, gB + 4 * i);
    }
    CP_COMMIT();
#pragma unroll
    for (int i = 0; i < 4; i++) {
        CP_ASYNC16(dA + TG_BUFB + 16 * i, gA + 32 + 4 * i);
        CP_ASYNC16(dB + TG_BUFB + 16 * i, gB + 32 + 4 * i);
    }
    CP_COMMIT();

    for (int it = 0; it < NIT; it++) {
        if (it + 1 < NIT) CP_WAIT1(); else CP_WAIT0();
        __syncthreads();

        uint32_t oa = (uint32_t)(it & 1) * TG_BUFB;
#pragma unroll
        for (int ks = 0; ks < 4; ks++) {
            uint32_t af[4][4];
#pragma unroll
            for (int mt = 0; mt < 4; mt++)
                LDSM4(af[mt][0], af[mt][1], af[mt][2], af[mt][3],
                      aAddr[mt] + oa + ks * 32);
            uint32_t bf[4][2];
#pragma unroll
            for (int np = 0; np < 2; np++)
                LDSM4(bf[2 * np][0], bf[2 * np][1], bf[2 * np + 1][0], bf[2 * np + 1][1],
                      bAddr[np] + oa + ks * 32);
#pragma unroll
            for (int mt = 0; mt < 4; mt++)
#pragma unroll
                for (int nt = 0; nt < 4; nt++)
                    MMA_TF32(acc[mt][nt], af[mt], bf[nt]);
        }
        __syncthreads();

        if (it + 2 < NIT) {
            const float* ga = gA + (it + 2) * 32;
            const float* gb = gB + (it + 2) * 32;
            uint32_t da = dA + oa, db = dB + oa;   // reuse buffer just consumed
#pragma unroll
            for (int i = 0; i < 4; i++) {
                CP_ASYNC16(da + 16 * i, ga + 4 * i);
                CP_ASYNC16(db + 16 * i, gb + 4 * i);
            }
            CP_COMMIT();
        }
    }

    // epilogue: C fragment (row lr, cols 2*lc..+1; + row+8)
#pragma unroll
    for (int mt = 0; mt < 4; mt++) {
#pragma unroll
        for (int nt = 0; nt < 4; nt++) {
            int r = by * 128 + wm * 64 + mt * 16 + lr;
            int c = bx * 128 + wn * 32 + nt * 8 + 2 * lc;
            size_t off0 = (size_t)r * N + c;
            size_t off1 = (size_t)(r + 8) * N + c;
            float2 lo = make_float2(acc[mt][nt][0], acc[mt][nt][1]);
            float2 hi = make_float2(acc[mt][nt][2], acc[mt][nt][3]);
            if (Cadd) {
                float2 x0 = *(const float2*)(Cadd + off0);
                float2 x1 = *(const float2*)(Cadd + off1);
                lo.x += x0.x; lo.y += x0.y;
                hi.x += x1.x; hi.y += x1.y;
            }
            *(float2*)(C + off0) = lo;
            *(float2*)(C + off1) = hi;
        }
    }
}

__global__ void __launch_bounds__(256, 2) tgemm_nt(
    const float* __restrict__ A, const float* __restrict__ Bm,
    const float* __restrict__ Cadd, float* __restrict__ C, int N, int K)
{
    gemm_body(A, Bm, Cadd, C, N, K, blockIdx.x, blockIdx.y);
}

// fused k+v projection: blockIdx.x 0-3 -> wk/g_k0, 4-7 -> wv/g_v0
__global__ void __launch_bounds__(256, 2) tgemm_kv(
    const float* __restrict__ A, const float* __restrict__ Wk,
    const float* __restrict__ Wv, float* __restrict__ Ck, float* __restrict__ Cv)
{
    int sel = blockIdx.x >> 2;
    gemm_body(A, sel ? Wv : Wk, nullptr, sel ? Cv : Ck,
              PROJ, DD, blockIdx.x & 3, blockIdx.y);
}

// ---------------- gate: g0[t,h] = sigmoid(x0[t,:] . wg[h,:]) ----------------
__global__ __launch_bounds__(256) void gate_kernel(
    const float* __restrict__ x, const float* __restrict__ wg)
{
    int warp = (blockIdx.x * blockDim.x + threadIdx.x) >> 5;
    int lane = threadIdx.x & 31;
    if (warp >= SS) return;
    float acc[NHH];
#pragma unroll
    for (int h = 0; h < NHH; h++) acc[h] = 0.f;
    const float* xr = x + (size_t)warp * DD;
    for (int d = lane; d < DD; d += 32) {
        float xv = xr[d];
#pragma unroll
        for (int h = 0; h < NHH; h++) acc[h] += xv * wg[h * DD + d];
    }
#pragma unroll
    for (int h = 0; h < NHH; h++) {
        float v = acc[h];
#pragma unroll
        for (int o = 16; o > 0; o >>= 1) v += __shfl_down_sync(0xffffffffu, v, o);
        if (lane == 0) g_g0[warp * NHH + h] = 1.f / (1.f + expf(-v));
    }
}

// ---------------- per-chunk decayed write sum: W_c[h] = K_hat^T V ----------------
__global__ __launch_bounds__(256) void chunkw_kernel()
{
    __shared__ float Ks[32][68];
    __shared__ float Vs[32][68];
    int h = blockIdx.x, c = blockIdx.y;
    int t = threadIdx.x, tx = t & 15, ty = t >> 4;

    float acc[4][4];
#pragma unroll
    for (int i = 0; i < 4; i++)
#pragma unroll
        for (int j = 0; j < 4; j++) acc[i][j] = 0.f;

    for (int jt = 0; jt < 4; jt++) {
#pragma unroll
        for (int pp = 0; pp < 2; pp++) {
            int p = t * 2 + pp;
            int j = p >> 4, kk4 = (p & 15) << 2;
            int row = c * CHUNK + jt * 32 + j;
            float s = g_dpow[127 - (jt * 32 + j)] * 0.1f * g_g0[row * NHH + h];
            float4 kv = *(const float4*)(g_k0 + (size_t)row * PROJ + h * 64 + kk4);
            Ks[j][kk4+0] = kv.x * s; Ks[j][kk4+1] = kv.y * s;
            Ks[j][kk4+2] = kv.z * s; Ks[j][kk4+3] = kv.w * s;
            float4 vv = *(const float4*)(g_v0 + (size_t)row * PROJ + h * 64 + kk4);
            Vs[j][kk4+0] = vv.x; Vs[j][kk4+1] = vv.y;
            Vs[j][kk4+2] = vv.z; Vs[j][kk4+3] = vv.w;
        }
        __syncthreads();
#pragma unroll
        for (int j = 0; j < 32; j++) {
            float kr[4], vr[4];
            *(float4*)kr = *(const float4*)&Ks[j][ty * 4];
            *(float4*)vr = *(const float4*)&Vs[j][tx * 4];
#pragma unroll
            for (int ii = 0; ii < 4; ii++)
#pragma unroll
                for (int jj = 0; jj < 4; jj++)
                    acc[ii][jj] += kr[ii] * vr[jj];
        }
        __syncthreads();
    }
#pragma unroll
    for (int ii = 0; ii < 4; ii++) {
        float4 o = make_float4(acc[ii][0], acc[ii][1], acc[ii][2], acc[ii][3]);
        *(float4*)(g_W + ((size_t)(c * NHH + h) * 64 + ty * 4 + ii) * 64 + tx * 4) = o;
    }
}

// ---------------- elementwise state prefix scan over chunks ----------------
__global__ void scan_kernel()
{
    int e = blockIdx.x * blockDim.x + threadIdx.x;   // 0..32767
    float fw = 0.f;
    float dc = g_dpow[128];
#pragma unroll 1
    for (int c = 0; c < NC; c++) {
        g_Fst[(size_t)c * STATE_SZ + e] = fw;
        fw = dc * fw + g_W[(size_t)c * STATE_SZ + e];
    }
}

// ---------------- retrieval: R = Lam*(Q F) + (mask.decay.gate . QK^T) V ----------------
#define QS_STR 68
#define AS_STR 33
#define SM_QS  0
#define SM_FS  (128*68)
#define SM_AS  (128*68 + 64*68)
#define SM_KT  (128*68 + 64*68 + 128*33)
#define SM_VT  (SM_KT + 32*68)
#define SM_SG  (SM_VT + 32*68)
#define RETR_SMEM_BYTES ((SM_SG + 128) * 4)

__global__ __launch_bounds__(256) void retrieve_kernel()
{
    extern __shared__ float sm[];
    float* Qs  = sm + SM_QS;
    float* Fs  = sm + SM_FS;
    float* Asm = sm + SM_AS;
    float* Kt  = sm + SM_KT;
    float* Vt  = sm + SM_VT;
    float* sg  = sm + SM_SG;

    int h = blockIdx.x, c = blockIdx.y, b = blockIdx.z;
    int t = threadIdx.x;

#pragma unroll
    for (int pp = 0; pp < 8; pp++) {
        int p = t + 256 * pp;
        int i = p >> 4, kk4 = (p & 15) << 2;
        int row = b * SS + c * CHUNK + i;
        float4 v = *(const float4*)(g_q + (size_t)row * PROJ + h * 64 + kk4);
        Qs[i * QS_STR + kk4+0] = v.x; Qs[i * QS_STR + kk4+1] = v.y;
        Qs[i * QS_STR + kk4+2] = v.z; Qs[i * QS_STR + kk4+3] = v.w;
    }
#pragma unroll
    for (int pp = 0; pp < 4; pp++) {
        int p = t + 256 * pp;
        int kk = p >> 4, vv4 = (p & 15) << 2;
        float4 v = *(const float4*)(g_Fst + (size_t)c * STATE_SZ + h * 4096 + kk * 64 + vv4);
        Fs[kk * QS_STR + vv4+0] = v.x; Fs[kk * QS_STR + vv4+1] = v.y;
        Fs[kk * QS_STR + vv4+2] = v.z; Fs[kk * QS_STR + vv4+3] = v.w;
    }
    if (t < 128) sg[t] = 0.1f * g_g0[(c * CHUNK + t) * NHH + h];
    __syncthreads();

    int rx = t & 15, ry = t >> 4;
    float racc[8][4];
#pragma unroll
    for (int i = 0; i < 8; i++)
#pragma unroll
        for (int j = 0; j < 4; j++) racc[i][j] = 0.f;

#pragma unroll 4
    for (int kk = 0; kk < 64; kk++) {
        float4 fv = *(const float4*)&Fs[kk * QS_STR + rx * 4];
#pragma unroll
        for (int ii = 0; ii < 8; ii++) {
            float qv = Qs[(ry * 8 + ii) * QS_STR + kk];
            racc[ii][0] += qv * fv.x; racc[ii][1] += qv * fv.y;
            racc[ii][2] += qv * fv.z; racc[ii][3] += qv * fv.w;
        }
    }
#pragma unroll
    for (int ii = 0; ii < 8; ii++) {
        float lam = g_dpow[ry * 8 + ii];
        racc[ii][0] *= lam; racc[ii][1] *= lam; racc[ii][2] *= lam; racc[ii][3] *= lam;
    }

    int ax = t & 7, ay = t >> 3;

    for (int jt = 0; jt < 4; jt++) {
        __syncthreads();
#pragma unroll
        for (int pp = 0; pp < 2; pp++) {
            int p = t * 2 + pp;
            int j = p >> 4, kk4 = (p & 15) << 2;
            int row = c * CHUNK + jt * 32 + j;
            float4 kv = *(const float4*)(g_k0 + (size_t)row * PROJ + h * 64 + kk4);
            Kt[j * QS_STR + kk4+0] = kv.x; Kt[j * QS_STR + kk4+1] = kv.y;
            Kt[j * QS_STR + kk4+2] = kv.z; Kt[j * QS_STR + kk4+3] = kv.w;
            float4 vv = *(const float4*)(g_v0 + (size_t)row * PROJ + h * 64 + kk4);
            Vt[j * QS_STR + kk4+0] = vv.x; Vt[j * QS_STR + kk4+1] = vv.y;
            Vt[j * QS_STR + kk4+2] = vv.z; Vt[j * QS_STR + kk4+3] = vv.w;
        }
        __syncthreads();

        float aacc[4][4];
#pragma unroll
        for (int i = 0; i < 4; i++)
#pragma unroll
            for (int j = 0; j < 4; j++) aacc[i][j] = 0.f;
#pragma unroll 4
        for (int kk4 = 0; kk4 < 64; kk4 += 4) {
            float4 qv[4], kv[4];
#pragma unroll
            for (int ii = 0; ii < 4; ii++)
                qv[ii] = *(const float4*)&Qs[(ay * 4 + ii) * QS_STR + kk4];
#pragma unroll
            for (int jj = 0; jj < 4; jj++)
                kv[jj] = *(const float4*)&Kt[(ax * 4 + jj) * QS_STR + kk4];
#pragma unroll
            for (int ii = 0; ii < 4; ii++)
#pragma unroll
                for (int jj = 0; jj < 4; jj++)
                    aacc[ii][jj] += qv[ii].x * kv[jj].x + qv[ii].y * kv[jj].y
                                  + qv[ii].z * kv[jj].z + qv[ii].w * kv[jj].w;
        }
#pragma unroll
        for (int ii = 0; ii < 4; ii++) {
            int i = ay * 4 + ii;
#pragma unroll
            for (int jj = 0; jj < 4; jj++) {
                int jl = ax * 4 + jj;
                int jg = jt * 32 + jl;
                float w = (jg < i) ? g_dpow[i - 1 - jg] * sg[jg] : 0.f;
                Asm[i * AS_STR + jl] = aacc[ii][jj] * w;
            }
        }
        __syncthreads();

#pragma unroll 8
        for (int j = 0; j < 32; j++) {
            float4 vv = *(const float4*)&Vt[j * QS_STR + rx * 4];
#pragma unroll
            for (int ii = 0; ii < 8; ii++) {
                float a = Asm[(ry * 8 + ii) * AS_STR + j];
                racc[ii][0] += a * vv.x; racc[ii][1] += a * vv.y;
                racc[ii][2] += a * vv.z; racc[ii][3] += a * vv.w;
            }
        }
    }

#pragma unroll
    for (int ii = 0; ii < 8; ii++) {
        int row = b * SS + c * CHUNK + ry * 8 + ii;
        float4 o = make_float4(racc[ii][0], racc[ii][1], racc[ii][2], racc[ii][3]);
        *(float4*)(g_retr + (size_t)row * PROJ + h * 64 + rx * 4) = o;
    }
}

// ---------------- host launch ----------------
extern "C" void kernel_launch(void* const* d_in, const int* in_sizes, int n_in,
                              void* d_out, int out_size)
{
    (void)in_sizes; (void)n_in; (void)out_size;
    const float* x  = (const float*)d_in[0];
    const float* wk = (const float*)d_in[1];
    const float* wv = (const float*)d_in[2];
    const float* wq = (const float*)d_in[3];
    const float* wg = (const float*)d_in[4];
    const float* wo = (const float*)d_in[5];
    float* out = (float*)d_out;

    float *qp, *k0p, *v0p, *retrp;
    cudaGetSymbolAddress((void**)&qp,    g_q);
    cudaGetSymbolAddress((void**)&k0p,   g_k0);
    cudaGetSymbolAddress((void**)&v0p,   g_v0);
    cudaGetSymbolAddress((void**)&retrp, g_retr);

    cudaFuncSetAttribute(retrieve_kernel,
                         cudaFuncAttributeMaxDynamicSharedMemorySize,
                         RETR_SMEM_BYTES);
    cudaFuncSetAttribute(tgemm_nt,
                         cudaFuncAttributeMaxDynamicSharedMemorySize, TG_SMEM);
    cudaFuncSetAttribute(tgemm_kv,
                         cudaFuncAttributeMaxDynamicSharedMemorySize, TG_SMEM);

    dpow_init_kernel<<<1, 1>>>();

    // projections on tensor cores (tf32); k/v fused, batch 0 only
    tgemm_nt<<<dim3(4, 128), 256, TG_SMEM>>>(x, wq, nullptr, qp, PROJ, DD);
    tgemm_kv<<<dim3(8, 32),  256, TG_SMEM>>>(x, wk, wv, k0p, v0p);
    gate_kernel<<<512, 256>>>(x, wg);

    // chunked linear-attention decomposition of the scan
    chunkw_kernel<<<dim3(NHH, NC), 256>>>();
    scan_kernel<<<128, 256>>>();
    retrieve_kernel<<<dim3(NHH, NC, BB), 256, RETR_SMEM_BYTES>>>();

    // out = x + retrieved @ w_out^T
    tgemm_nt<<<dim3(6, 128), 256, TG_SMEM>>>(retrp, wo, x, out, DD, PROJ);
}

// round 7
// speedup vs baseline: 2.3969x; 1.4373x over previous
#include <cuda_runtime.h>
#include <stdint.h>
#include <math.h>

// Problem constants
#define BB      4
#define SS      4096
#define DD      768
#define NHH     8
#define DKV     64
#define PROJ    512          // NH*DK = NH*DV
#define NTOK    16384        // B*S
#define CHUNK   128
#define NC      32           // S / CHUNK
#define STATE_SZ 32768       // NH*DK*DV

// ---------------- device scratch (static, no allocation) ----------------
__device__ float g_q   [NTOK * PROJ];       // q for all batches
__device__ float g_k0  [SS * PROJ];         // k, batch 0 only
__device__ float g_v0  [SS * PROJ];         // v, batch 0 only
__device__ float g_g0  [SS * NHH];          // gate, batch 0 only
__device__ float g_W   [NC * STATE_SZ];     // per-chunk decayed write sums
__device__ float g_Fst [NC * STATE_SZ];     // state at each chunk start
__device__ float g_retr[NTOK * PROJ];       // retrieved
__device__ float g_dpow[136];               // 0.95^i, i=0..128

// ---------------- decay power table ----------------
__global__ void dpow_init_kernel() {
    if (threadIdx.x == 0 && blockIdx.x == 0) {
        double p = 1.0;
        for (int i = 0; i <= 128; i++) { g_dpow[i] = (float)p; p *= 0.95; }
    }
}

// ---------------- tensor-core plumbing ----------------
#define MMA_TF32(d, a, b)                                                     \
    asm volatile("mma.sync.aligned.m16n8k8.row.col.f32.tf32.tf32.f32 "        \
                 "{%0,%1,%2,%3}, {%4,%5,%6,%7}, {%8,%9}, {%0,%1,%2,%3};"      \
                 : "+f"((d)[0]), "+f"((d)[1]), "+f"((d)[2]), "+f"((d)[3])     \
                 : "r"((a)[0]), "r"((a)[1]), "r"((a)[2]), "r"((a)[3]),        \
                   "r"((b)[0]), "r"((b)[1]))

#define LDSM4(r0, r1, r2, r3, addr)                                           \
    asm volatile("ldmatrix.sync.aligned.m8n8.x4.shared.b16 {%0,%1,%2,%3}, [%4];" \
                 : "=r"(r0), "=r"(r1), "=r"(r2), "=r"(r3) : "r"(addr))

#define CP_ASYNC16(dst, src)                                                  \
    asm volatile("cp.async.cg.shared.global [%0], [%1], 16;" :: "r"(dst), "l"(src))
#define CP_COMMIT() asm volatile("cp.async.commit_group;")
#define CP_WAIT1()  asm volatile("cp.async.wait_group 1;")
#define CP_WAIT0()  asm volatile("cp.async.wait_group 0;")

// ================= projection GEMM =================
// 128x128 block, BK=32, 256 threads = 8 warps (2x4), warp tile 64x32.
// 3-stage cp.async pipeline, one __syncthreads per K-iter.
// Smem row-major, pitch 36 floats (conflict-free: bank=(4r+c) mod 32).
#define TG_P      36
#define TG_BUFB   (128 * TG_P * 4)             // bytes per stage buffer (18432)
#define TG_SMEM   (6 * TG_BUFB)                // A[3] + B[3] = 110592 bytes

__device__ __forceinline__ void gemm_body(
    const float* __restrict__ A, const float* __restrict__ Bm,
    const float* __restrict__ Cadd, float* __restrict__ C,
    int N, int K, int bx, int by)
{
    extern __shared__ float smg[];
    uint32_t sA = (uint32_t)__cvta_generic_to_shared(smg);
    uint32_t sB = sA + 3 * TG_BUFB;

    int t    = threadIdx.x;
    int warp = t >> 5, lane = t & 31;
    int wm = warp >> 2, wn = warp & 3;     // warp grid 2 x 4
    int g  = lane >> 3, gr = lane & 7;     // ldmatrix groups
    int lr = lane >> 2, lc = lane & 3;     // mma C-fragment decomposition

    int ldr = t & 127, ldc = (t >> 7) * 16;
    const float* gA = A  + (size_t)(by * 128 + ldr) * K + ldc;
    const float* gB = Bm + (size_t)(bx * 128 + ldr) * K + ldc;
    uint32_t dA = sA + (uint32_t)(ldr * TG_P + ldc) * 4;
    uint32_t dB = sB + (uint32_t)(ldr * TG_P + ldc) * 4;

    uint32_t aAddr[4];
#pragma unroll
    for (int mt = 0; mt < 4; mt++)
        aAddr[mt] = sA + (uint32_t)(((wm * 64 + mt * 16 + (g & 1) * 8 + gr) * TG_P
                                     + (g >> 1) * 4) * 4);
    uint32_t bAddr[2];
#pragma unroll
    for (int np = 0; np < 2; np++)
        bAddr[np] = sB + (uint32_t)(((wn * 32 + (2 * np + (g >> 1)) * 8 + gr) * TG_P
                                     + (g & 1) * 4) * 4);

    float acc[4][4][4];
#pragma unroll
    for (int i = 0; i < 4; i++)
#pragma unroll
        for (int j = 0; j < 4; j++)
#pragma unroll
            for (int r = 0; r < 4; r++) acc[i][j][r] = 0.f;

    const int NIT = K >> 5;

    // prologue: stages 0 and 1
#pragma unroll
    for (int i = 0; i < 4; i++) {
        CP_ASYNC16(dA + 16 * i, gA + 4 * i);
        CP_ASYNC16(dB + 16 * i, gB + 4 * i);
    }
    CP_COMMIT();
#pragma unroll
    for (int i = 0; i < 4; i++) {
        CP_ASYNC16(dA + TG_BUFB + 16 * i, gA + 32 + 4 * i);
        CP_ASYNC16(dB + TG_BUFB + 16 * i, gB + 32 + 4 * i);
    }
    CP_COMMIT();

    int st = 0;                        // it % 3
    int st2 = 2;                       // (it+2) % 3
    for (int it = 0; it < NIT; it++) {
        if (it < NIT - 1) CP_WAIT1(); else CP_WAIT0();
        __syncthreads();

        uint32_t oa = (uint32_t)st * TG_BUFB;
#pragma unroll
        for (int ks = 0; ks < 4; ks++) {
            uint32_t af[4][4];
#pragma unroll
            for (int mt = 0; mt < 4; mt++)
                LDSM4(af[mt][0], af[mt][1], af[mt][2], af[mt][3],
                      aAddr[mt] + oa + ks * 32);
            uint32_t bf[4][2];
#pragma unroll
            for (int np = 0; np < 2; np++)
                LDSM4(bf[2 * np][0], bf[2 * np][1], bf[2 * np + 1][0], bf[2 * np + 1][1],
                      bAddr[np] + oa + ks * 32);
#pragma unroll
            for (int mt = 0; mt < 4; mt++)
#pragma unroll
                for (int nt = 0; nt < 4; nt++)
                    MMA_TF32(acc[mt][nt], af[mt], bf[nt]);
        }

        // refill stage (it+2)%3 == stage consumed at it-1 (all warps past top sync)
        if (it + 2 < NIT) {
            const float* ga = gA + (it + 2) * 32;
            const float* gb = gB + (it + 2) * 32;
            uint32_t o2 = (uint32_t)st2 * TG_BUFB;
#pragma unroll
            for (int i = 0; i < 4; i++) {
                CP_ASYNC16(dA + o2 + 16 * i, ga + 4 * i);
                CP_ASYNC16(dB + o2 + 16 * i, gb + 4 * i);
            }
            CP_COMMIT();
        }
        st  = (st  == 2) ? 0 : st  + 1;
        st2 = (st2 == 2) ? 0 : st2 + 1;
    }

    // epilogue
#pragma unroll
    for (int mt = 0; mt < 4; mt++) {
#pragma unroll
        for (int nt = 0; nt < 4; nt++) {
            int r = by * 128 + wm * 64 + mt * 16 + lr;
            int c = bx * 128 + wn * 32 + nt * 8 + 2 * lc;
            size_t off0 = (size_t)r * N + c;
            size_t off1 = (size_t)(r + 8) * N + c;
            float2 lo = make_float2(acc[mt][nt][0], acc[mt][nt][1]);
            float2 hi = make_float2(acc[mt][nt][2], acc[mt][nt][3]);
            if (Cadd) {
                float2 x0 = *(const float2*)(Cadd + off0);
                float2 x1 = *(const float2*)(Cadd + off1);
                lo.x += x0.x; lo.y += x0.y;
                hi.x += x1.x; hi.y += x1.y;
            }
            *(float2*)(C + off0) = lo;
            *(float2*)(C + off1) = hi;
        }
    }
}

__global__ void __launch_bounds__(256, 2) tgemm_nt(
    const float* __restrict__ A, const float* __restrict__ Bm,
    const float* __restrict__ Cadd, float* __restrict__ C, int N, int K)
{
    gemm_body(A, Bm, Cadd, C, N, K, blockIdx.x, blockIdx.y);
}

// fused k+v projection: blockIdx.x 0-3 -> wk/g_k0, 4-7 -> wv/g_v0
__global__ void __launch_bounds__(256, 2) tgemm_kv(
    const float* __restrict__ A, const float* __restrict__ Wk,
    const float* __restrict__ Wv, float* __restrict__ Ck, float* __restrict__ Cv)
{
    int sel = blockIdx.x >> 2;
    gemm_body(A, sel ? Wv : Wk, nullptr, sel ? Cv : Ck,
              PROJ, DD, blockIdx.x & 3, blockIdx.y);
}

// ---------------- gate: g0[t,h] = sigmoid(x0[t,:] . wg[h,:]) ----------------
__global__ __launch_bounds__(256) void gate_kernel(
    const float* __restrict__ x, const float* __restrict__ wg)
{
    int warp = (blockIdx.x * blockDim.x + threadIdx.x) >> 5;
    int lane = threadIdx.x & 31;
    if (warp >= SS) return;
    float acc[NHH];
#pragma unroll
    for (int h = 0; h < NHH; h++) acc[h] = 0.f;
    const float* xr = x + (size_t)warp * DD;
    for (int d = lane; d < DD; d += 32) {
        float xv = xr[d];
#pragma unroll
        for (int h = 0; h < NHH; h++) acc[h] += xv * wg[h * DD + d];
    }
#pragma unroll
    for (int h = 0; h < NHH; h++) {
        float v = acc[h];
#pragma unroll
        for (int o = 16; o > 0; o >>= 1) v += __shfl_down_sync(0xffffffffu, v, o);
        if (lane == 0) g_g0[warp * NHH + h] = 1.f / (1.f + expf(-v));
    }
}

// ---------------- per-chunk decayed write sum: W_c[h] = K_hat^T V ----------------
__global__ __launch_bounds__(256) void chunkw_kernel()
{
    __shared__ float Ks[32][68];
    __shared__ float Vs[32][68];
    int h = blockIdx.x, c = blockIdx.y;
    int t = threadIdx.x, tx = t & 15, ty = t >> 4;

    float acc[4][4];
#pragma unroll
    for (int i = 0; i < 4; i++)
#pragma unroll
        for (int j = 0; j < 4; j++) acc[i][j] = 0.f;

    for (int jt = 0; jt < 4; jt++) {
#pragma unroll
        for (int pp = 0; pp < 2; pp++) {
            int p = t * 2 + pp;
            int j = p >> 4, kk4 = (p & 15) << 2;
            int row = c * CHUNK + jt * 32 + j;
            float s = g_dpow[127 - (jt * 32 + j)] * 0.1f * g_g0[row * NHH + h];
            float4 kv = *(const float4*)(g_k0 + (size_t)row * PROJ + h * 64 + kk4);
            Ks[j][kk4+0] = kv.x * s; Ks[j][kk4+1] = kv.y * s;
            Ks[j][kk4+2] = kv.z * s; Ks[j][kk4+3] = kv.w * s;
            float4 vv = *(const float4*)(g_v0 + (size_t)row * PROJ + h * 64 + kk4);
            Vs[j][kk4+0] = vv.x; Vs[j][kk4+1] = vv.y;
            Vs[j][kk4+2] = vv.z; Vs[j][kk4+3] = vv.w;
        }
        __syncthreads();
#pragma unroll
        for (int j = 0; j < 32; j++) {
            float kr[4], vr[4];
            *(float4*)kr = *(const float4*)&Ks[j][ty * 4];
            *(float4*)vr = *(const float4*)&Vs[j][tx * 4];
#pragma unroll
            for (int ii = 0; ii < 4; ii++)
#pragma unroll
                for (int jj = 0; jj < 4; jj++)
                    acc[ii][jj] += kr[ii] * vr[jj];
        }
        __syncthreads();
    }
#pragma unroll
    for (int ii = 0; ii < 4; ii++) {
        float4 o = make_float4(acc[ii][0], acc[ii][1], acc[ii][2], acc[ii][3]);
        *(float4*)(g_W + ((size_t)(c * NHH + h) * 64 + ty * 4 + ii) * 64 + tx * 4) = o;
    }
}

// ---------------- elementwise state prefix scan over chunks ----------------
__global__ void scan_kernel()
{
    int e = blockIdx.x * blockDim.x + threadIdx.x;   // 0..32767
    float fw = 0.f;
    float dc = g_dpow[128];
#pragma unroll 1
    for (int c = 0; c < NC; c++) {
        g_Fst[(size_t)c * STATE_SZ + e] = fw;
        fw = dc * fw + g_W[(size_t)c * STATE_SZ + e];
    }
}

// ================= tensor-core retrieval =================
// R = Lam*(Q F) + (mask.decay.gate o QK^T) V  per (h, chunk, batch) tile.
// 256 threads = 8 warps (4 row-groups x 2 col-groups).
// Pitches: 68 (Qs/Ft/Kt) and 36 (Vt/As); both == 4 mod 32 -> conflict-free.
#define RT_QP 68
#define RT_SP 36
#define RS_QS 0
#define RS_FT (RS_QS + 128 * RT_QP)            // 8704
#define RS_KT (RS_FT + 64 * RT_QP)             // 13056
#define RS_VT (RS_KT + 32 * RT_QP)             // 15232
#define RS_AS (RS_VT + 64 * RT_SP)             // 17536
#define RS_SG (RS_AS + 128 * RT_SP)            // 22144
#define RT_SMEM ((RS_SG + 128) * 4)            // 89088 bytes

__global__ void __launch_bounds__(256, 2) retrieve_tc()
{
    extern __shared__ float sm[];
    uint32_t sbase = (uint32_t)__cvta_generic_to_shared(sm);
    int h = blockIdx.x, c = blockIdx.y, b = blockIdx.z;
    int t = threadIdx.x;
    int warp = t >> 5, lane = t & 31;
    int wr = warp >> 1, wc = warp & 1;     // 4 x 2 warp grid
    int g  = lane >> 3, gr = lane & 7;
    int lr = lane >> 2, lc = lane & 3;

    float* Qs = sm + RS_QS;   // [i 128][k 64]   pitch 68
    float* Ft = sm + RS_FT;   // [v 64][k 64]    pitch 68 (F transposed)
    float* Kt = sm + RS_KT;   // [j 32][k 64]    pitch 68
    float* Vt = sm + RS_VT;   // [v 64][j 32]    pitch 36 (V transposed)
    float* As = sm + RS_AS;   // [i 128][j 32]   pitch 36
    float* sg = sm + RS_SG;   // [128]

    // -- load Q (straight) --
#pragma unroll
    for (int pp = 0; pp < 8; pp++) {
        int p = t + 256 * pp;
        int i = p >> 4, k4 = (p & 15) << 2;
        float4 v = *(const float4*)(g_q + (size_t)(b * SS + c * CHUNK + i) * PROJ + h * 64 + k4);
        Qs[i * RT_QP + k4 + 0] = v.x; Qs[i * RT_QP + k4 + 1] = v.y;
        Qs[i * RT_QP + k4 + 2] = v.z; Qs[i * RT_QP + k4 + 3] = v.w;
    }
    // -- load F transposed: Ft[v][k] = F[k][v] --
#pragma unroll
    for (int pp = 0; pp < 4; pp++) {
        int p = t + 256 * pp;
        int k = p >> 4, v4 = (p & 15) << 2;
        float4 v = *(const float4*)(g_Fst + (size_t)c * STATE_SZ + h * 4096 + k * 64 + v4);
        Ft[(v4 + 0) * RT_QP + k] = v.x; Ft[(v4 + 1) * RT_QP + k] = v.y;
        Ft[(v4 + 2) * RT_QP + k] = v.z; Ft[(v4 + 3) * RT_QP + k] = v.w;
    }
    if (t < 128) sg[t] = 0.1f * g_g0[(c * CHUNK + t) * NHH + h];
    __syncthreads();

    // ldmatrix base addresses
    uint32_t qA[2], aA[2], fB[2], vB[2], kB;
#pragma unroll
    for (int mt = 0; mt < 2; mt++) {
        qA[mt] = sbase + (uint32_t)((RS_QS + (wr * 32 + mt * 16 + (g & 1) * 8 + gr) * RT_QP
                                     + (g >> 1) * 4) * 4);
        aA[mt] = sbase + (uint32_t)((RS_AS + (wr * 32 + mt * 16 + (g & 1) * 8 + gr) * RT_SP
                                     + (g >> 1) * 4) * 4);
    }
#pragma unroll
    for (int np = 0; np < 2; np++) {
        fB[np] = sbase + (uint32_t)((RS_FT + (wc * 32 + (2 * np + (g >> 1)) * 8 + gr) * RT_QP
                                     + (g & 1) * 4) * 4);
        vB[np] = sbase + (uint32_t)((RS_VT + (wc * 32 + (2 * np + (g >> 1)) * 8 + gr) * RT_SP
                                     + (g & 1) * 4) * 4);
    }
    kB = sbase + (uint32_t)((RS_KT + (wc * 16 + (g >> 1) * 8 + gr) * RT_QP + (g & 1) * 4) * 4);

    float racc[2][4][4];
#pragma unroll
    for (int i = 0; i < 2; i++)
#pragma unroll
        for (int j = 0; j < 4; j++)
#pragma unroll
            for (int r = 0; r < 4; r++) racc[i][j][r] = 0.f;

    // -- inter-chunk: R = Q @ F  (k = 64, 8 ks) --
#pragma unroll
    for (int ks = 0; ks < 8; ks++) {
        uint32_t af[2][4], bf[4][2];
#pragma unroll
        for (int mt = 0; mt < 2; mt++)
            LDSM4(af[mt][0], af[mt][1], af[mt][2], af[mt][3], qA[mt] + ks * 32);
#pragma unroll
        for (int np = 0; np < 2; np++)
            LDSM4(bf[2 * np][0], bf[2 * np][1], bf[2 * np + 1][0], bf[2 * np + 1][1],
                  fB[np] + ks * 32);
#pragma unroll
        for (int mt = 0; mt < 2; mt++)
#pragma unroll
            for (int nt = 0; nt < 4; nt++)
                MMA_TF32(racc[mt][nt], af[mt], bf[nt]);
    }
    // scale by Lambda_i = decay^i (QF part only)
#pragma unroll
    for (int mt = 0; mt < 2; mt++) {
        int r0 = wr * 32 + mt * 16 + lr;
        float l0 = g_dpow[r0], l1 = g_dpow[r0 + 8];
#pragma unroll
        for (int nt = 0; nt < 4; nt++) {
            racc[mt][nt][0] *= l0; racc[mt][nt][1] *= l0;
            racc[mt][nt][2] *= l1; racc[mt][nt][3] *= l1;
        }
    }

    // -- intra-chunk: 4 tiles of 32 keys --
    for (int jt = 0; jt < 4; jt++) {
        __syncthreads();               // prior AV reads of Kt/Vt/As complete
        // load K tile (straight) and V tile (transposed)
#pragma unroll
        for (int pp = 0; pp < 2; pp++) {
            int p = t + 256 * pp;
            int j = p >> 4, k4 = (p & 15) << 2;
            int row = c * CHUNK + jt * 32 + j;
            float4 kv = *(const float4*)(g_k0 + (size_t)row * PROJ + h * 64 + k4);
            Kt[j * RT_QP + k4 + 0] = kv.x; Kt[j * RT_QP + k4 + 1] = kv.y;
            Kt[j * RT_QP + k4 + 2] = kv.z; Kt[j * RT_QP + k4 + 3] = kv.w;
            float4 vv = *(const float4*)(g_v0 + (size_t)row * PROJ + h * 64 + k4);
            Vt[(k4 + 0) * RT_SP + j] = vv.x; Vt[(k4 + 1) * RT_SP + j] = vv.y;
            Vt[(k4 + 2) * RT_SP + j] = vv.z; Vt[(k4 + 3) * RT_SP + j] = vv.w;
        }
        __syncthreads();

        // A = Q @ K^T  (128 x 32, warp tile 32 x 16)
        float qk[2][2][4];
#pragma unroll
        for (int i = 0; i < 2; i++)
#pragma unroll
            for (int j = 0; j < 2; j++)
#pragma unroll
                for (int r = 0; r < 4; r++) qk[i][j][r] = 0.f;
#pragma unroll
        for (int ks = 0; ks < 8; ks++) {
            uint32_t af[2][4], bf[2][2];
#pragma unroll
            for (int mt = 0; mt < 2; mt++)
                LDSM4(af[mt][0], af[mt][1], af[mt][2], af[mt][3], qA[mt] + ks * 32);
            LDSM4(bf[0][0], bf[0][1], bf[1][0], bf[1][1], kB + ks * 32);
#pragma unroll
            for (int mt = 0; mt < 2; mt++)
#pragma unroll
                for (int nt = 0; nt < 2; nt++)
                    MMA_TF32(qk[mt][nt], af[mt], bf[nt]);
        }

        // mask * decay * gate, store to As
#pragma unroll
        for (int mt = 0; mt < 2; mt++) {
            int i0 = wr * 32 + mt * 16 + lr, i1 = i0 + 8;
#pragma unroll
            for (int nt = 0; nt < 2; nt++) {
                int jl = wc * 16 + nt * 8 + 2 * lc;
                int jg0 = jt * 32 + jl, jg1 = jg0 + 1;
                float w;
                w = (jg0 < i0) ? g_dpow[i0 - 1 - jg0] * sg[jg0] : 0.f;
                As[i0 * RT_SP + jl]     = qk[mt][nt][0] * w;
                w = (jg1 < i0) ? g_dpow[i0 - 1 - jg1] * sg[jg1] : 0.f;
                As[i0 * RT_SP + jl + 1] = qk[mt][nt][1] * w;
                w = (jg0 < i1) ? g_dpow[i1 - 1 - jg0] * sg[jg0] : 0.f;
                As[i1 * RT_SP + jl]     = qk[mt][nt][2] * w;
                w = (jg1 < i1) ? g_dpow[i1 - 1 - jg1] * sg[jg1] : 0.f;
                As[i1 * RT_SP + jl + 1] = qk[mt][nt][3] * w;
            }
        }
        __syncthreads();

        // R += A @ V  (k = 32, 4 ks)
#pragma unroll
        for (int ks = 0; ks < 4; ks++) {
            uint32_t af[2][4], bf[4][2];
#pragma unroll
            for (int mt = 0; mt < 2; mt++)
                LDSM4(af[mt][0], af[mt][1], af[mt][2], af[mt][3], aA[mt] + ks * 32);
#pragma unroll
            for (int np = 0; np < 2; np++)
                LDSM4(bf[2 * np][0], bf[2 * np][1], bf[2 * np + 1][0], bf[2 * np + 1][1],
                      vB[np] + ks * 32);
#pragma unroll
            for (int mt = 0; mt < 2; mt++)
#pragma unroll
                for (int nt = 0; nt < 4; nt++)
                    MMA_TF32(racc[mt][nt], af[mt], bf[nt]);
        }
    }

    // store R
#pragma unroll
    for (int mt = 0; mt < 2; mt++) {
#pragma unroll
        for (int nt = 0; nt < 4; nt++) {
            int i = wr * 32 + mt * 16 + lr;
            int v = wc * 32 + nt * 8 + 2 * lc;
            size_t off0 = (size_t)(b * SS + c * CHUNK + i) * PROJ + h * 64 + v;
            size_t off1 = (size_t)(b * SS + c * CHUNK + i + 8) * PROJ + h * 64 + v;
            *(float2*)(g_retr + off0) = make_float2(racc[mt][nt][0], racc[mt][nt][1]);
            *(float2*)(g_retr + off1) = make_float2(racc[mt][nt][2], racc[mt][nt][3]);
        }
    }
}

// ---------------- host launch ----------------
extern "C" void kernel_launch(void* const* d_in, const int* in_sizes, int n_in,
                              void* d_out, int out_size)
{
    (void)in_sizes; (void)n_in; (void)out_size;
    const float* x  = (const float*)d_in[0];
    const float* wk = (const float*)d_in[1];
    const float* wv = (const float*)d_in[2];
    const float* wq = (const float*)d_in[3];
    const float* wg = (const float*)d_in[4];
    const float* wo = (const float*)d_in[5];
    float* out = (float*)d_out;

    float *qp, *k0p, *v0p, *retrp;
    cudaGetSymbolAddress((void**)&qp,    g_q);
    cudaGetSymbolAddress((void**)&k0p,   g_k0);
    cudaGetSymbolAddress((void**)&v0p,   g_v0);
    cudaGetSymbolAddress((void**)&retrp, g_retr);

    cudaFuncSetAttribute(retrieve_tc,
                         cudaFuncAttributeMaxDynamicSharedMemorySize, RT_SMEM);
    cudaFuncSetAttribute(tgemm_nt,
                         cudaFuncAttributeMaxDynamicSharedMemorySize, TG_SMEM);
    cudaFuncSetAttribute(tgemm_kv,
                         cudaFuncAttributeMaxDynamicSharedMemorySize, TG_SMEM);

    dpow_init_kernel<<<1, 1>>>();

    // projections on tensor cores (tf32); k/v fused, batch 0 only
    tgemm_nt<<<dim3(4, 128), 256, TG_SMEM>>>(x, wq, nullptr, qp, PROJ, DD);
    tgemm_kv<<<dim3(8, 32),  256, TG_SMEM>>>(x, wk, wv, k0p, v0p);
    gate_kernel<<<512, 256>>>(x, wg);

    // chunked linear-attention decomposition of the scan
    chunkw_kernel<<<dim3(NHH, NC), 256>>>();
    scan_kernel<<<128, 256>>>();
    retrieve_tc<<<dim3(NHH, NC, BB), 256, RT_SMEM>>>();

    // out = x + retrieved @ w_out^T
    tgemm_nt<<<dim3(6, 128), 256, TG_SMEM>>>(retrp, wo, x, out, DD, PROJ);
}

// round 9
// speedup vs baseline: 2.5024x; 1.0440x over previous
#include <cuda_runtime.h>
#include <stdint.h>
#include <math.h>

// Problem constants
#define BB      4
#define SS      4096
#define DD      768
#define NHH     8
#define DKV     64
#define PROJ    512          // NH*DK = NH*DV
#define NTOK    16384        // B*S
#define CHUNK   128
#define NC      32           // S / CHUNK
#define STATE_SZ 32768       // NH*DK*DV

// ---------------- device scratch (static, no allocation) ----------------
__device__ float g_q   [NTOK * PROJ];
__device__ float g_k0  [SS * PROJ];
__device__ float g_v0  [SS * PROJ];
__device__ float g_g0  [SS * NHH];
__device__ float g_W   [NC * STATE_SZ];
__device__ float g_Fst [NC * STATE_SZ];
__device__ float g_retr[NTOK * PROJ];
__device__ float g_dpow[136];

__global__ void dpow_init_kernel() {
    if (threadIdx.x == 0 && blockIdx.x == 0) {
        double p = 1.0;
        for (int i = 0; i <= 128; i++) { g_dpow[i] = (float)p; p *= 0.95; }
    }
}

// ---------------- tensor-core plumbing (legacy mma path; tcgen05 is not
// available: harness builds compute_103 PTX which ptxas rejects for tcgen05) --
#define MMA_TF32(d, a, b)                                                     \
    asm volatile("mma.sync.aligned.m16n8k8.row.col.f32.tf32.tf32.f32 "        \
                 "{%0,%1,%2,%3}, {%4,%5,%6,%7}, {%8,%9}, {%0,%1,%2,%3};"      \
                 : "+f"((d)[0]), "+f"((d)[1]), "+f"((d)[2]), "+f"((d)[3])     \
                 : "r"((a)[0]), "r"((a)[1]), "r"((a)[2]), "r"((a)[3]),        \
                   "r"((b)[0]), "r"((b)[1]))

#define LDSM4(r0, r1, r2, r3, addr)                                           \
    asm volatile("ldmatrix.sync.aligned.m8n8.x4.shared.b16 {%0,%1,%2,%3}, [%4];" \
                 : "=r"(r0), "=r"(r1), "=r"(r2), "=r"(r3) : "r"(addr))

#define CP_ASYNC16(dst, src)                                                  \
    asm volatile("cp.async.cg.shared.global [%0], [%1], 16;" :: "r"(dst), "l"(src))
#define CP_COMMIT() asm volatile("cp.async.commit_group;")
#define CP_WAIT1()  asm volatile("cp.async.wait_group 1;")
#define CP_WAIT0()  asm volatile("cp.async.wait_group 0;")

// ================= projection GEMM body =================
// 128x128 block, BK=32, 256 threads = 8 warps (2x4), warp tile 64x32.
// 3-stage cp.async pipeline, one __syncthreads per K-iter.
// Smem row-major, pitch 36 floats (conflict-free: bank=(4r+c) mod 32).
#define TG_P      36
#define TG_BUFB   (128 * TG_P * 4)             // bytes per stage buffer (18432)
#define TG_SMEM   (6 * TG_BUFB)                // A[3] + B[3] = 110592 bytes

// mode 0: C[r][c] (+Cadd) normal store.  mode 1: gate — write sigmoid of
// cols 0..7 into g_g0[token*NHH+col]; B has only 8 valid rows (bmask=7).
__device__ __forceinline__ void gemm_body(
    const float* __restrict__ A, const float* __restrict__ Bm,
    const float* __restrict__ Cadd, float* __restrict__ C,
    int N, int K, int bx, int by, int bmask, int mode)
{
    extern __shared__ float smg[];
    uint32_t sA = (uint32_t)__cvta_generic_to_shared(smg);
    uint32_t sB = sA + 3 * TG_BUFB;

    int t    = threadIdx.x;
    int warp = t >> 5, lane = t & 31;
    int wm = warp >> 2, wn = warp & 3;     // warp grid 2 x 4
    int g  = lane >> 3, gr = lane & 7;     // ldmatrix groups
    int lr = lane >> 2, lc = lane & 3;     // mma C-fragment decomposition

    int ldr = t & 127, ldc = (t >> 7) * 16;
    const float* gA = A  + (size_t)(by * 128 + ldr) * K + ldc;
    const float* gB = Bm + (size_t)(bx * 128 + (ldr & bmask)) * K + ldc;
    uint32_t dA = sA + (uint32_t)(ldr * TG_P + ldc) * 4;
    uint32_t dB = sB + (uint32_t)(ldr * TG_P + ldc) * 4;

    uint32_t aAddr[4];
#pragma unroll
    for (int mt = 0; mt < 4; mt++)
        aAddr[mt] = sA + (uint32_t)(((wm * 64 + mt * 16 + (g & 1) * 8 + gr) * TG_P
                                     + (g >> 1) * 4) * 4);
    uint32_t bAddr[2];
#pragma unroll
    for (int np = 0; np < 2; np++)
        bAddr[np] = sB + (uint32_t)(((wn * 32 + (2 * np + (g >> 1)) * 8 + gr) * TG_P
                                     + (g & 1) * 4) * 4);

    float acc[4][4][4];
#pragma unroll
    for (int i = 0; i < 4; i++)
#pragma unroll
        for (int j = 0; j < 4; j++)
#pragma unroll
            for (int r = 0; r < 4; r++) acc[i][j][r] = 0.f;

    const int NIT = K >> 5;

    // prologue: stages 0 and 1
#pragma unroll
    for (int i = 0; i < 4; i++) {
        CP_ASYNC16(dA + 16 * i, gA + 4 * i);
        CP_ASYNC16(dB + 16 * i, gB + 4 * i);
    }
    CP_COMMIT();
#pragma unroll
    for (int i = 0; i < 4; i++) {
        CP_ASYNC16(dA + TG_BUFB + 16 * i, gA + 32 + 4 * i);
        CP_ASYNC16(dB + TG_BUFB + 16 * i, gB + 32 + 4 * i);
    }
    CP_COMMIT();

    int st = 0, st2 = 2;
    for (int it = 0; it < NIT; it++) {
        if (it < NIT - 1) CP_WAIT1(); else CP_WAIT0();
        __syncthreads();

        uint32_t oa = (uint32_t)st * TG_BUFB;
#pragma unroll
        for (int ks = 0; ks < 4; ks++) {
            uint32_t af[4][4];
#pragma unroll
            for (int mt = 0; mt < 4; mt++)
                LDSM4(af[mt][0], af[mt][1], af[mt][2], af[mt][3],
                      aAddr[mt] + oa + ks * 32);
            uint32_t bf[4][2];
#pragma unroll
            for (int np = 0; np < 2; np++)
                LDSM4(bf[2 * np][0], bf[2 * np][1], bf[2 * np + 1][0], bf[2 * np + 1][1],
                      bAddr[np] + oa + ks * 32);
#pragma unroll
            for (int mt = 0; mt < 4; mt++)
#pragma unroll
                for (int nt = 0; nt < 4; nt++)
                    MMA_TF32(acc[mt][nt], af[mt], bf[nt]);
        }

        if (it + 2 < NIT) {
            const float* ga = gA + (it + 2) * 32;
            const float* gb = gB + (it + 2) * 32;
            uint32_t o2 = (uint32_t)st2 * TG_BUFB;
#pragma unroll
            for (int i = 0; i < 4; i++) {
                CP_ASYNC16(dA + o2 + 16 * i, ga + 4 * i);
                CP_ASYNC16(dB + o2 + 16 * i, gb + 4 * i);
            }
            CP_COMMIT();
        }
        st  = (st  == 2) ? 0 : st  + 1;
        st2 = (st2 == 2) ? 0 : st2 + 1;
    }

    if (mode == 1) {
        // gate: only cols 0..7 valid (wn==0, nt==0, 2*lc<8 always true)
        if (wn == 0) {
#pragma unroll
            for (int mt = 0; mt < 4; mt++) {
                int r0 = by * 128 + wm * 64 + mt * 16 + lr;
                int c  = 2 * lc;
                if (c < NHH) {
                    g_g0[r0 * NHH + c]           = 1.f / (1.f + expf(-acc[mt][0][0]));
                    g_g0[r0 * NHH + c + 1]       = 1.f / (1.f + expf(-acc[mt][0][1]));
                    g_g0[(r0 + 8) * NHH + c]     = 1.f / (1.f + expf(-acc[mt][0][2]));
                    g_g0[(r0 + 8) * NHH + c + 1] = 1.f / (1.f + expf(-acc[mt][0][3]));
                }
            }
        }
        return;
    }

#pragma unroll
    for (int mt = 0; mt < 4; mt++) {
#pragma unroll
        for (int nt = 0; nt < 4; nt++) {
            int r = by * 128 + wm * 64 + mt * 16 + lr;
            int c = bx * 128 + wn * 32 + nt * 8 + 2 * lc;
            size_t off0 = (size_t)r * N + c;
            size_t off1 = (size_t)(r + 8) * N + c;
            float2 lo = make_float2(acc[mt][nt][0], acc[mt][nt][1]);
            float2 hi = make_float2(acc[mt][nt][2], acc[mt][nt][3]);
            if (Cadd) {
                float2 x0 = *(const float2*)(Cadd + off0);
                float2 x1 = *(const float2*)(Cadd + off1);
                lo.x += x0.x; lo.y += x0.y;
                hi.x += x1.x; hi.y += x1.y;
            }
            *(float2*)(C + off0) = lo;
            *(float2*)(C + off1) = hi;
        }
    }
}

// out-projection (standalone)
__global__ void __launch_bounds__(256, 2) tgemm_nt(
    const float* __restrict__ A, const float* __restrict__ Bm,
    const float* __restrict__ Cadd, float* __restrict__ C, int N, int K)
{
    gemm_body(A, Bm, Cadd, C, N, K, blockIdx.x, blockIdx.y, 127, 0);
}

// merged front-end: q-proj (512 blocks) + k/v-proj (256) + gate (32)
__global__ void __launch_bounds__(256, 2) proj_all(
    const float* __restrict__ x,  const float* __restrict__ wq,
    const float* __restrict__ wk, const float* __restrict__ wv,
    const float* __restrict__ wg,
    float* __restrict__ qp, float* __restrict__ k0p, float* __restrict__ v0p)
{
    int bid = blockIdx.x;
    if (bid < 512) {
        gemm_body(x, wq, nullptr, qp, PROJ, DD, bid & 3, bid >> 2, 127, 0);
    } else if (bid < 768) {
        int i = bid - 512;
        int bx = i & 7, by = i >> 3;
        int sel = bx >> 2;
        gemm_body(x, sel ? wv : wk, nullptr, sel ? v0p : k0p,
                  PROJ, DD, bx & 3, by, 127, 0);
    } else {
        int by = bid - 768;                 // 0..31 over batch-0 tokens
        gemm_body(x, wg, nullptr, nullptr, NHH, DD, 0, by, 7, 1);
    }
}

// ---------------- per-chunk decayed write sum ----------------
__global__ __launch_bounds__(256) void chunkw_kernel()
{
    __shared__ float Ks[32][68];
    __shared__ float Vs[32][68];
    int h = blockIdx.x, c = blockIdx.y;
    int t = threadIdx.x, tx = t & 15, ty = t >> 4;

    float acc[4][4];
#pragma unroll
    for (int i = 0; i < 4; i++)
#pragma unroll
        for (int j = 0; j < 4; j++) acc[i][j] = 0.f;

    for (int jt = 0; jt < 4; jt++) {
#pragma unroll
        for (int pp = 0; pp < 2; pp++) {
            int p = t * 2 + pp;
            int j = p >> 4, kk4 = (p & 15) << 2;
            int row = c * CHUNK + jt * 32 + j;
            float s = g_dpow[127 - (jt * 32 + j)] * 0.1f * g_g0[row * NHH + h];
            float4 kv = *(const float4*)(g_k0 + (size_t)row * PROJ + h * 64 + kk4);
            Ks[j][kk4+0] = kv.x * s; Ks[j][kk4+1] = kv.y * s;
            Ks[j][kk4+2] = kv.z * s; Ks[j][kk4+3] = kv.w * s;
            float4 vv = *(const float4*)(g_v0 + (size_t)row * PROJ + h * 64 + kk4);
            Vs[j][kk4+0] = vv.x; Vs[j][kk4+1] = vv.y;
            Vs[j][kk4+2] = vv.z; Vs[j][kk4+3] = vv.w;
        }
        __syncthreads();
#pragma unroll
        for (int j = 0; j < 32; j++) {
            float kr[4], vr[4];
            *(float4*)kr = *(const float4*)&Ks[j][ty * 4];
            *(float4*)vr = *(const float4*)&Vs[j][tx * 4];
#pragma unroll
            for (int ii = 0; ii < 4; ii++)
#pragma unroll
                for (int jj = 0; jj < 4; jj++)
                    acc[ii][jj] += kr[ii] * vr[jj];
        }
        __syncthreads();
    }
#pragma unroll
    for (int ii = 0; ii < 4; ii++) {
        float4 o = make_float4(acc[ii][0], acc[ii][1], acc[ii][2], acc[ii][3]);
        *(float4*)(g_W + ((size_t)(c * NHH + h) * 64 + ty * 4 + ii) * 64 + tx * 4) = o;
    }
}

// ---------------- state prefix scan over chunks ----------------
__global__ void scan_kernel()
{
    int e = blockIdx.x * blockDim.x + threadIdx.x;
    float fw = 0.f;
    float dc = g_dpow[128];
#pragma unroll 1
    for (int c = 0; c < NC; c++) {
        g_Fst[(size_t)c * STATE_SZ + e] = fw;
        fw = dc * fw + g_W[(size_t)c * STATE_SZ + e];
    }
}

// ================= tensor-core retrieval =================
#define RT_QP 68
#define RT_SP 36
#define RS_QS 0
#define RS_FT (RS_QS + 128 * RT_QP)
#define RS_KT (RS_FT + 64 * RT_QP)
#define RS_VT (RS_KT + 32 * RT_QP)
#define RS_AS (RS_VT + 64 * RT_SP)
#define RS_SG (RS_AS + 128 * RT_SP)
#define RT_SMEM ((RS_SG + 128) * 4)

__global__ void __launch_bounds__(256, 2) retrieve_tc()
{
    extern __shared__ float sm[];
    uint32_t sbase = (uint32_t)__cvta_generic_to_shared(sm);
    int h = blockIdx.x, c = blockIdx.y, b = blockIdx.z;
    int t = threadIdx.x;
    int warp = t >> 5, lane = t & 31;
    int wr = warp >> 1, wc = warp & 1;
    int g  = lane >> 3, gr = lane & 7;
    int lr = lane >> 2, lc = lane & 3;

    float* Qs = sm + RS_QS;
    float* Ft = sm + RS_FT;
    float* Kt = sm + RS_KT;
    float* Vt = sm + RS_VT;
    float* As = sm + RS_AS;
    float* sg = sm + RS_SG;

#pragma unroll
    for (int pp = 0; pp < 8; pp++) {
        int p = t + 256 * pp;
        int i = p >> 4, k4 = (p & 15) << 2;
        float4 v = *(const float4*)(g_q + (size_t)(b * SS + c * CHUNK + i) * PROJ + h * 64 + k4);
        Qs[i * RT_QP + k4 + 0] = v.x; Qs[i * RT_QP + k4 + 1] = v.y;
        Qs[i * RT_QP + k4 + 2] = v.z; Qs[i * RT_QP + k4 + 3] = v.w;
    }
#pragma unroll
    for (int pp = 0; pp < 4; pp++) {
        int p = t + 256 * pp;
        int k = p >> 4, v4 = (p & 15) << 2;
        float4 v = *(const float4*)(g_Fst + (size_t)c * STATE_SZ + h * 4096 + k * 64 + v4);
        Ft[(v4 + 0) * RT_QP + k] = v.x; Ft[(v4 + 1) * RT_QP + k] = v.y;
        Ft[(v4 + 2) * RT_QP + k] = v.z; Ft[(v4 + 3) * RT_QP + k] = v.w;
    }
    if (t < 128) sg[t] = 0.1f * g_g0[(c * CHUNK + t) * NHH + h];
    __syncthreads();

    uint32_t qA[2], aA[2], fB[2], vB[2], kB;
#pragma unroll
    for (int mt = 0; mt < 2; mt++) {
        qA[mt] = sbase + (uint32_t)((RS_QS + (wr * 32 + mt * 16 + (g & 1) * 8 + gr) * RT_QP
                                     + (g >> 1) * 4) * 4);
        aA[mt] = sbase + (uint32_t)((RS_AS + (wr * 32 + mt * 16 + (g & 1) * 8 + gr) * RT_SP
                                     + (g >> 1) * 4) * 4);
    }
#pragma unroll
    for (int np = 0; np < 2; np++) {
        fB[np] = sbase + (uint32_t)((RS_FT + (wc * 32 + (2 * np + (g >> 1)) * 8 + gr) * RT_QP
                                     + (g & 1) * 4) * 4);
        vB[np] = sbase + (uint32_t)((RS_VT + (wc * 32 + (2 * np + (g >> 1)) * 8 + gr) * RT_SP
                                     + (g & 1) * 4) * 4);
    }
    kB = sbase + (uint32_t)((RS_KT + (wc * 16 + (g >> 1) * 8 + gr) * RT_QP + (g & 1) * 4) * 4);

    float racc[2][4][4];
#pragma unroll
    for (int i = 0; i < 2; i++)
#pragma unroll
        for (int j = 0; j < 4; j++)
#pragma unroll
            for (int r = 0; r < 4; r++) racc[i][j][r] = 0.f;

#pragma unroll
    for (int ks = 0; ks < 8; ks++) {
        uint32_t af[2][4], bf[4][2];
#pragma unroll
        for (int mt = 0; mt < 2; mt++)
            LDSM4(af[mt][0], af[mt][1], af[mt][2], af[mt][3], qA[mt] + ks * 32);
#pragma unroll
        for (int np = 0; np < 2; np++)
            LDSM4(bf[2 * np][0], bf[2 * np][1], bf[2 * np + 1][0], bf[2 * np + 1][1],
                  fB[np] + ks * 32);
#pragma unroll
        for (int mt = 0; mt < 2; mt++)
#pragma unroll
            for (int nt = 0; nt < 4; nt++)
                MMA_TF32(racc[mt][nt], af[mt], bf[nt]);
    }
#pragma unroll
    for (int mt = 0; mt < 2; mt++) {
        int r0 = wr * 32 + mt * 16 + lr;
        float l0 = g_dpow[r0], l1 = g_dpow[r0 + 8];
#pragma unroll
        for (int nt = 0; nt < 4; nt++) {
            racc[mt][nt][0] *= l0; racc[mt][nt][1] *= l0;
            racc[mt][nt][2] *= l1; racc[mt][nt][3] *= l1;
        }
    }

    for (int jt = 0; jt < 4; jt++) {
        __syncthreads();
#pragma unroll
        for (int pp = 0; pp < 2; pp++) {
            int p = t + 256 * pp;
            int j = p >> 4, k4 = (p & 15) << 2;
            int row = c * CHUNK + jt * 32 + j;
            float4 kv = *(const float4*)(g_k0 + (size_t)row * PROJ + h * 64 + k4);
            Kt[j * RT_QP + k4 + 0] = kv.x; Kt[j * RT_QP + k4 + 1] = kv.y;
            Kt[j * RT_QP + k4 + 2] = kv.z; Kt[j * RT_QP + k4 + 3] = kv.w;
            float4 vv = *(const float4*)(g_v0 + (size_t)row * PROJ + h * 64 + k4);
            Vt[(k4 + 0) * RT_SP + j] = vv.x; Vt[(k4 + 1) * RT_SP + j] = vv.y;
            Vt[(k4 + 2) * RT_SP + j] = vv.z; Vt[(k4 + 3) * RT_SP + j] = vv.w;
        }
        __syncthreads();

        float qk[2][2][4];
#pragma unroll
        for (int i = 0; i < 2; i++)
#pragma unroll
            for (int j = 0; j < 2; j++)
#pragma unroll
                for (int r = 0; r < 4; r++) qk[i][j][r] = 0.f;
#pragma unroll
        for (int ks = 0; ks < 8; ks++) {
            uint32_t af[2][4], bf[2][2];
#pragma unroll
            for (int mt = 0; mt < 2; mt++)
                LDSM4(af[mt][0], af[mt][1], af[mt][2], af[mt][3], qA[mt] + ks * 32);
            LDSM4(bf[0][0], bf[0][1], bf[1][0], bf[1][1], kB + ks * 32);
#pragma unroll
            for (int mt = 0; mt < 2; mt++)
#pragma unroll
                for (int nt = 0; nt < 2; nt++)
                    MMA_TF32(qk[mt][nt], af[mt], bf[nt]);
        }

#pragma unroll
        for (int mt = 0; mt < 2; mt++) {
            int i0 = wr * 32 + mt * 16 + lr, i1 = i0 + 8;
#pragma unroll
            for (int nt = 0; nt < 2; nt++) {
                int jl = wc * 16 + nt * 8 + 2 * lc;
                int jg0 = jt * 32 + jl, jg1 = jg0 + 1;
                float w;
                w = (jg0 < i0) ? g_dpow[i0 - 1 - jg0] * sg[jg0] : 0.f;
                As[i0 * RT_SP + jl]     = qk[mt][nt][0] * w;
                w = (jg1 < i0) ? g_dpow[i0 - 1 - jg1] * sg[jg1] : 0.f;
                As[i0 * RT_SP + jl + 1] = qk[mt][nt][1] * w;
                w = (jg0 < i1) ? g_dpow[i1 - 1 - jg0] * sg[jg0] : 0.f;
                As[i1 * RT_SP + jl]     = qk[mt][nt][2] * w;
                w = (jg1 < i1) ? g_dpow[i1 - 1 - jg1] * sg[jg1] : 0.f;
                As[i1 * RT_SP + jl + 1] = qk[mt][nt][3] * w;
            }
        }
        __syncthreads();

#pragma unroll
        for (int ks = 0; ks < 4; ks++) {
            uint32_t af[2][4], bf[4][2];
#pragma unroll
            for (int mt = 0; mt < 2; mt++)
                LDSM4(af[mt][0], af[mt][1], af[mt][2], af[mt][3], aA[mt] + ks * 32);
#pragma unroll
            for (int np = 0; np < 2; np++)
                LDSM4(bf[2 * np][0], bf[2 * np][1], bf[2 * np + 1][0], bf[2 * np + 1][1],
                      vB[np] + ks * 32);
#pragma unroll
            for (int mt = 0; mt < 2; mt++)
#pragma unroll
                for (int nt = 0; nt < 4; nt++)
                    MMA_TF32(racc[mt][nt], af[mt], bf[nt]);
        }
    }

#pragma unroll
    for (int mt = 0; mt < 2; mt++) {
#pragma unroll
        for (int nt = 0; nt < 4; nt++) {
            int i = wr * 32 + mt * 16 + lr;
            int v = wc * 32 + nt * 8 + 2 * lc;
            size_t off0 = (size_t)(b * SS + c * CHUNK + i) * PROJ + h * 64 + v;
            size_t off1 = (size_t)(b * SS + c * CHUNK + i + 8) * PROJ + h * 64 + v;
            *(float2*)(g_retr + off0) = make_float2(racc[mt][nt][0], racc[mt][nt][1]);
            *(float2*)(g_retr + off1) = make_float2(racc[mt][nt][2], racc[mt][nt][3]);
        }
    }
}

// ---------------- host launch ----------------
extern "C" void kernel_launch(void* const* d_in, const int* in_sizes, int n_in,
                              void* d_out, int out_size)
{
    (void)in_sizes; (void)n_in; (void)out_size;
    const float* x  = (const float*)d_in[0];
    const float* wk = (const float*)d_in[1];
    const float* wv = (const float*)d_in[2];
    const float* wq = (const float*)d_in[3];
    const float* wg = (const float*)d_in[4];
    const float* wo = (const float*)d_in[5];
    float* out = (float*)d_out;

    float *qp, *k0p, *v0p, *retrp;
    cudaGetSymbolAddress((void**)&qp,    g_q);
    cudaGetSymbolAddress((void**)&k0p,   g_k0);
    cudaGetSymbolAddress((void**)&v0p,   g_v0);
    cudaGetSymbolAddress((void**)&retrp, g_retr);

    cudaFuncSetAttribute(retrieve_tc,
                         cudaFuncAttributeMaxDynamicSharedMemorySize, RT_SMEM);
    cudaFuncSetAttribute(tgemm_nt,
                         cudaFuncAttributeMaxDynamicSharedMemorySize, TG_SMEM);
    cudaFuncSetAttribute(proj_all,
                         cudaFuncAttributeMaxDynamicSharedMemorySize, TG_SMEM);

    dpow_init_kernel<<<1, 1>>>();

    // merged front-end: q-proj + k/v-proj + gate in one 800-block launch
    proj_all<<<800, 256, TG_SMEM>>>(x, wq, wk, wv, wg, qp, k0p, v0p);

    // chunked linear-attention decomposition of the scan
    chunkw_kernel<<<dim3(NHH, NC), 256>>>();
    scan_kernel<<<128, 256>>>();
    retrieve_tc<<<dim3(NHH, NC, BB), 256, RT_SMEM>>>();

    // out = x + retrieved @ w_out^T
    tgemm_nt<<<dim3(6, 128), 256, TG_SMEM>>>(retrp, wo, x, out, DD, PROJ);
}